// round 7
// baseline (speedup 1.0000x reference)
#include <cuda_runtime.h>
#include <cuda_bf16.h>
#include <math.h>
#include <stdint.h>

// Problem dims
#define TT 512
#define BB 64
#define EE 512
#define HD 512
#define HH 1024
#define CC 16
#define START_TAG 14
#define STOP_TAG 15
#define NG 4096          // 2 dirs * 4 gates * HD
#define MROWS (TT*BB)    // 32768

// ---------------- scratch ------------------------------------------------------
__device__ float g_X0[(size_t)MROWS * EE];
__device__ float g_G [(size_t)MROWS * NG];
__device__ float g_H0[(size_t)MROWS * HH];
__device__ float g_H1[(size_t)MROWS * HH];
__device__ __nv_bfloat16 g_As[(size_t)MROWS * 6 * HH];
__device__ __nv_bfloat16 g_Ws[(size_t)NG * 6 * HH];
__device__ float g_feats[(size_t)BB * TT * CC];
__device__ float g_hbuf[2 * 2 * BB * HD];

__device__ unsigned int g_bar_count;
__device__ unsigned int g_bar_gen;

__device__ __forceinline__ void grid_barrier(int nblk) {
    __syncthreads();
    if (threadIdx.x == 0) {
        __threadfence();
        unsigned int gen = *(volatile unsigned int*)&g_bar_gen;
        if (atomicAdd(&g_bar_count, 1u) == (unsigned)(nblk - 1)) {
            g_bar_count = 0;
            __threadfence();
            atomicAdd(&g_bar_gen, 1u);
        } else {
            unsigned int cur;
            do {
                asm volatile("ld.acquire.gpu.u32 %0, [%1];"
                             : "=r"(cur) : "l"(&g_bar_gen));
            } while (cur == gen);
        }
    }
    __syncthreads();
}

__device__ __forceinline__ uint32_t smem_u32(const void* p) {
    uint32_t a;
    asm("{ .reg .u64 t; cvta.to.shared.u64 t, %1; cvt.u32.u64 %0, t; }"
        : "=r"(a) : "l"(p));
    return a;
}

// ---------------- embedding gather ---------------------------------------------
__global__ void embed_kernel(const int* __restrict__ sent,
                             const float* __restrict__ emb,
                             float* __restrict__ X0) {
    int m = blockIdx.x;
    int t = m >> 6;
    int b = m & 63;
    int tok = sent[b * TT + t];
    const float4* src = reinterpret_cast<const float4*>(emb + (size_t)tok * EE);
    float4* dst = reinterpret_cast<float4*>(X0 + (size_t)m * EE);
    dst[threadIdx.x] = src[threadIdx.x];
}

// ---------------- fp32 -> 3-term bf16 split (K-concatenated, exact) ------------
__global__ void splitA_kernel(const float* __restrict__ X,
                              __nv_bfloat16* __restrict__ Y,
                              int K, long long total) {
    long long idx = (long long)blockIdx.x * blockDim.x + threadIdx.x;
    if (idx >= total) return;
    int m = (int)(idx / K);
    int k = (int)(idx % K);
    float a = X[idx];
    __nv_bfloat16 b0 = __float2bfloat16(a);
    float r = a - __bfloat162float(b0);
    __nv_bfloat16 b1 = __float2bfloat16(r);
    float r2 = r - __bfloat162float(b1);
    __nv_bfloat16 b2 = __float2bfloat16(r2);
    __nv_bfloat16* base = Y + (size_t)m * 6 * K + k;
    base[0 * K] = b0; base[1 * K] = b0; base[2 * K] = b1;
    base[3 * K] = b0; base[4 * K] = b1; base[5 * K] = b2;
}
__global__ void splitW_kernel(const float* __restrict__ X,
                              __nv_bfloat16* __restrict__ Y,
                              int K, long long total) {
    long long idx = (long long)blockIdx.x * blockDim.x + threadIdx.x;
    if (idx >= total) return;
    int m = (int)(idx / K);
    int k = (int)(idx % K);
    float a = X[idx];
    __nv_bfloat16 b0 = __float2bfloat16(a);
    float r = a - __bfloat162float(b0);
    __nv_bfloat16 b1 = __float2bfloat16(r);
    float r2 = r - __bfloat162float(b1);
    __nv_bfloat16 b2 = __float2bfloat16(r2);
    __nv_bfloat16* base = Y + (size_t)m * 6 * K + k;
    base[0 * K] = b0; base[1 * K] = b1; base[2 * K] = b0;
    base[3 * K] = b2; base[4 * K] = b1; base[5 * K] = b0;
}

// ================= pipelined warp-mma bf16 GEMM (2 CTAs/SM) =====================
// C[M][NG] = A(MxK6) * W(NGxK6)^T + b1 + b2.
// 128x128 tile, BK=32, 3-stage cp.async, 8 warps (2x4), 64x32 warp tiles.
#define BM 128
#define BN 128
#define BK 32
#define NSTAGE 3
#define PADH 40
#define SA_BYTES (BM * PADH * 2)             // 10240
#define SB_BYTES (BN * PADH * 2)             // 10240
#define GEMM_SMEM (NSTAGE * (SA_BYTES + SB_BYTES))   // 61440 -> 2 CTAs/SM

__device__ __forceinline__ void ldsm4(uint32_t addr, uint32_t r[4]) {
    asm volatile("ldmatrix.sync.aligned.m8n8.x4.shared.b16 {%0,%1,%2,%3}, [%4];"
                 : "=r"(r[0]), "=r"(r[1]), "=r"(r[2]), "=r"(r[3]) : "r"(addr));
}
__device__ __forceinline__ void mma16816(float c[4], const uint32_t a[4],
                                         const uint32_t b[2]) {
    asm volatile(
        "mma.sync.aligned.m16n8k16.row.col.f32.bf16.bf16.f32 "
        "{%0,%1,%2,%3}, {%4,%5,%6,%7}, {%8,%9}, {%0,%1,%2,%3};"
        : "+f"(c[0]), "+f"(c[1]), "+f"(c[2]), "+f"(c[3])
        : "r"(a[0]), "r"(a[1]), "r"(a[2]), "r"(a[3]), "r"(b[0]), "r"(b[1]));
}
__device__ __forceinline__ void cp16(uint32_t dst, const void* src) {
    asm volatile("cp.async.cg.shared.global [%0], [%1], 16;" :: "r"(dst), "l"(src));
}
__device__ __forceinline__ void cp_commit() {
    asm volatile("cp.async.commit_group;");
}
template <int N>
__device__ __forceinline__ void cp_wait() {
    asm volatile("cp.async.wait_group %0;" :: "n"(N));
}

__global__ void __launch_bounds__(256, 2)
gemm_mma(const __nv_bfloat16* __restrict__ A,
         const __nv_bfloat16* __restrict__ W,
         const float* __restrict__ b1,
         const float* __restrict__ b2,
         float* __restrict__ C,
         int K6) {
    extern __shared__ char dsm[];
    const uint32_t sAb = smem_u32(dsm);
    const uint32_t sBb = sAb + NSTAGE * SA_BYTES;

    const int tid = threadIdx.x;
    const int lane = tid & 31;
    const int wid = tid >> 5;
    const int warpm = wid >> 2;     // 0..1
    const int warpn = wid & 3;      // 0..3
    const int n0 = blockIdx.x * BN;
    const int m0 = blockIdx.y * BM;

    const int rowoff = ((lane >> 3) & 1) * 8 + (lane & 7);
    const int koffA  = (lane >> 4) * 8;
    const int noff   = ((lane >> 4) << 3) + (lane & 7);
    const int koffB  = ((lane >> 3) & 1) * 8;

    float acc[4][4][4];
#pragma unroll
    for (int i = 0; i < 4; i++)
#pragma unroll
        for (int j = 0; j < 4; j++)
#pragma unroll
            for (int q = 0; q < 4; q++) acc[i][j][q] = 0.f;

    // per-iter loads: A 2 x cp16 per thread, B 2 x cp16 per thread
    auto issue = [&](int stage, int kt) {
        const int kb = kt * BK;
        const uint32_t sa = sAb + stage * SA_BYTES;
        const uint32_t sb = sBb + stage * SB_BYTES;
#pragma unroll
        for (int q = 0; q < 2; q++) {
            int id = tid + q * 256;
            int r = id >> 2, c4 = id & 3;
            cp16(sa + (uint32_t)(r * PADH + c4 * 8) * 2,
                 A + (size_t)(m0 + r) * K6 + kb + c4 * 8);
        }
#pragma unroll
        for (int q = 0; q < 2; q++) {
            int id = tid + q * 256;
            int r = id >> 2, c4 = id & 3;
            cp16(sb + (uint32_t)(r * PADH + c4 * 8) * 2,
                 W + (size_t)(n0 + r) * K6 + kb + c4 * 8);
        }
    };

    issue(0, 0); cp_commit();
    issue(1, 1); cp_commit();

    const int nkt = K6 / BK;
    int stage = 0;
    for (int kt = 0; kt < nkt; kt++) {
        cp_wait<1>();
        __syncthreads();
        if (kt + 2 < nkt) {
            int ns = stage + 2; if (ns >= NSTAGE) ns -= NSTAGE;
            issue(ns, kt + 2);
        }
        cp_commit();

        const uint32_t sa = sAb + stage * SA_BYTES;
        const uint32_t sb = sBb + stage * SB_BYTES;
#pragma unroll
        for (int ks = 0; ks < 2; ks++) {
            uint32_t af[4][4];
            uint32_t bf[4][2];
#pragma unroll
            for (int mf = 0; mf < 4; mf++) {
                int mrow = warpm * 64 + mf * 16 + rowoff;
                ldsm4(sa + (uint32_t)(mrow * PADH + ks * 16 + koffA) * 2, af[mf]);
            }
#pragma unroll
            for (int p = 0; p < 2; p++) {
                uint32_t rr[4];
                int nrow = warpn * 32 + p * 16 + noff;
                ldsm4(sb + (uint32_t)(nrow * PADH + ks * 16 + koffB) * 2, rr);
                bf[2 * p][0] = rr[0];     bf[2 * p][1] = rr[1];
                bf[2 * p + 1][0] = rr[2]; bf[2 * p + 1][1] = rr[3];
            }
#pragma unroll
            for (int mf = 0; mf < 4; mf++)
#pragma unroll
                for (int nf = 0; nf < 4; nf++)
                    mma16816(acc[mf][nf], af[mf], bf[nf]);
        }
        if (++stage == NSTAGE) stage = 0;
    }

    // epilogue: fp32 + biases
#pragma unroll
    for (int nf = 0; nf < 4; nf++) {
        const int col = n0 + warpn * 32 + nf * 8 + (lane & 3) * 2;
        const float bx = b1[col] + b2[col];
        const float by = b1[col + 1] + b2[col + 1];
#pragma unroll
        for (int mf = 0; mf < 4; mf++) {
            const int row = m0 + warpm * 64 + mf * 16 + (lane >> 2);
            float2 v0 = make_float2(acc[mf][nf][0] + bx, acc[mf][nf][1] + by);
            float2 v1 = make_float2(acc[mf][nf][2] + bx, acc[mf][nf][3] + by);
            *reinterpret_cast<float2*>(C + (size_t)row * NG + col) = v0;
            *reinterpret_cast<float2*>(C + (size_t)(row + 8) * NG + col) = v1;
        }
    }
}

// ---------------- persistent bidirectional LSTM layer (unchanged from R6) -------
#define LS_WS 0                         // float Ws[512][32]   = 65536 B
#define LS_HS 65536                     // float Hs[2][16][68] = 8704 B
#define LS_GS (65536 + 8704)            // float gs[4][64][8]  = 8192 B
#define LSTM_SMEM (LS_GS + 8192)        // 82432 B

__global__ void __launch_bounds__(128)
lstm_layer(const float* __restrict__ G,
           const float* __restrict__ Whh,
           const float* __restrict__ h0,
           const float* __restrict__ c0,
           float* __restrict__ hbuf,
           float* __restrict__ Hcat) {
    extern __shared__ char dsm[];
    float (*Ws)[32]     = reinterpret_cast<float(*)[32]>(dsm + LS_WS);
    float (*Hs)[16][68] = reinterpret_cast<float(*)[16][68]>(dsm + LS_HS);
    float (*gs)[64][8]  = reinterpret_cast<float(*)[64][8]>(dsm + LS_GS);

    const int dir = blockIdx.y;
    const int u0 = blockIdx.x * 8;
    const int tid = threadIdx.x;
    const float* W = Whh + (size_t)dir * 2048 * HD;

    const int lcc = tid & 31;
    const int lgate = lcc >> 3;
    const int lu = u0 + (lcc & 7);
    const int lkq = tid >> 5;
    const int lb = tid & 63;
    const int hkq0 = tid >> 6;

    for (int kt = 0; kt < HD; kt += 16) {
        float4 v = *reinterpret_cast<const float4*>(
            &W[(size_t)(lgate * HD + lu) * HD + kt + lkq * 4]);
        Ws[kt + lkq * 4 + 0][lcc] = v.x; Ws[kt + lkq * 4 + 1][lcc] = v.y;
        Ws[kt + lkq * 4 + 2][lcc] = v.z; Ws[kt + lkq * 4 + 3][lcc] = v.w;
    }

    float cr[4];
#pragma unroll
    for (int i = 0; i < 4; i++) {
        int p = tid + i * 128;
        int b = p >> 3, ul = p & 7;
        size_t idx = (size_t)dir * BB * HD + b * HD + u0 + ul;
        cr[i] = c0[idx];
        hbuf[idx] = h0[idx];
    }
    grid_barrier(128);

    const int b0  = (tid >> 3) * 4;
    const int cg0 = (tid & 7) * 4;
    const int g0  = cg0 >> 3;
    const int ul0 = cg0 & 7;

    for (int s = 0; s < TT; s++) {
        const int t = dir ? (TT - 1 - s) : s;
        const float* h = hbuf + (size_t)(s & 1) * 2 * BB * HD
                              + (size_t)dir * BB * HD;
        float* ho = hbuf + (size_t)((s + 1) & 1) * 2 * BB * HD
                         + (size_t)dir * BB * HD;

#pragma unroll
        for (int itq = 0; itq < 2; itq++) {
            int kq = hkq0 + itq * 2;
            float4 v = *reinterpret_cast<const float4*>(&h[lb * HD + kq * 4]);
            Hs[0][kq * 4 + 0][lb] = v.x; Hs[0][kq * 4 + 1][lb] = v.y;
            Hs[0][kq * 4 + 2][lb] = v.z; Hs[0][kq * 4 + 3][lb] = v.w;
        }
        __syncthreads();

        float acc[4][4];
#pragma unroll
        for (int i = 0; i < 4; i++)
#pragma unroll
            for (int j = 0; j < 4; j++) acc[i][j] = 0.f;

        for (int kt16 = 0; kt16 < 32; kt16++) {
            const int cur = kt16 & 1;
            float4 pv0, pv1;
            const bool pf = (kt16 < 31);
            if (pf) {
                const int kb = (kt16 + 1) * 16;
                pv0 = *reinterpret_cast<const float4*>(&h[lb * HD + kb + hkq0 * 4]);
                pv1 = *reinterpret_cast<const float4*>(&h[lb * HD + kb + (hkq0 + 2) * 4]);
            }
#pragma unroll
            for (int k = 0; k < 16; k++) {
                float4 hv = *reinterpret_cast<const float4*>(&Hs[cur][k][b0]);
                float4 wv = *reinterpret_cast<const float4*>(&Ws[kt16 * 16 + k][cg0]);
                float ar[4] = {hv.x, hv.y, hv.z, hv.w};
                float br[4] = {wv.x, wv.y, wv.z, wv.w};
#pragma unroll
                for (int i = 0; i < 4; i++)
#pragma unroll
                    for (int j = 0; j < 4; j++) acc[i][j] += ar[i] * br[j];
            }
            if (pf) {
                const int nb = cur ^ 1;
                Hs[nb][hkq0 * 4 + 0][lb] = pv0.x; Hs[nb][hkq0 * 4 + 1][lb] = pv0.y;
                Hs[nb][hkq0 * 4 + 2][lb] = pv0.z; Hs[nb][hkq0 * 4 + 3][lb] = pv0.w;
                Hs[nb][(hkq0 + 2) * 4 + 0][lb] = pv1.x;
                Hs[nb][(hkq0 + 2) * 4 + 1][lb] = pv1.y;
                Hs[nb][(hkq0 + 2) * 4 + 2][lb] = pv1.z;
                Hs[nb][(hkq0 + 2) * 4 + 3][lb] = pv1.w;
            }
            __syncthreads();
        }

        const int row0 = t * BB;
#pragma unroll
        for (int i = 0; i < 4; i++) {
            int b = b0 + i;
            float4 gv = *reinterpret_cast<const float4*>(
                &G[(size_t)(row0 + b) * NG + dir * 2048 + g0 * HD + u0 + ul0]);
            gs[g0][b][ul0 + 0] = acc[i][0] + gv.x;
            gs[g0][b][ul0 + 1] = acc[i][1] + gv.y;
            gs[g0][b][ul0 + 2] = acc[i][2] + gv.z;
            gs[g0][b][ul0 + 3] = acc[i][3] + gv.w;
        }
        __syncthreads();

#pragma unroll
        for (int i = 0; i < 4; i++) {
            int p = tid + i * 128;
            int b = p >> 3;
            int ul = p & 7;
            int u = u0 + ul;
            float ig = gs[0][b][ul];
            float fg = gs[1][b][ul];
            float gg = gs[2][b][ul];
            float og = gs[3][b][ul];
            float si = 1.f / (1.f + expf(-ig));
            float sf = 1.f / (1.f + expf(-fg));
            float so = 1.f / (1.f + expf(-og));
            float cn = sf * cr[i] + si * tanhf(gg);
            float hn = so * tanhf(cn);
            cr[i] = cn;
            ho[b * HD + u] = hn;
            Hcat[(size_t)t * BB * HH + b * HH + dir * HD + u] = hn;
        }
        grid_barrier(128);
    }
}

// ---------------- final linear ---------------------------------------------------
__global__ void linear_feats(const float* __restrict__ H1,
                             const float* __restrict__ lw,
                             const float* __restrict__ lb,
                             float* __restrict__ feats) {
    int warp = (blockIdx.x * blockDim.x + threadIdx.x) >> 5;
    int lane = threadIdx.x & 31;
    if (warp >= MROWS) return;
    const float* hrow = H1 + (size_t)warp * HH;
    float acc[CC];
#pragma unroll
    for (int c = 0; c < CC; c++) acc[c] = 0.f;
    for (int k = lane; k < HH; k += 32) {
        float hv = hrow[k];
#pragma unroll
        for (int c = 0; c < CC; c++) acc[c] += hv * lw[c * HH + k];
    }
#pragma unroll
    for (int c = 0; c < CC; c++) {
        float v = acc[c];
#pragma unroll
        for (int o = 16; o; o >>= 1) v += __shfl_down_sync(0xffffffffu, v, o);
        if (lane == 0) {
            int t = warp >> 6, b = warp & 63;
            feats[((size_t)b * TT + t) * CC + c] = v + lb[c];
        }
    }
}

// ---------------- Viterbi decode --------------------------------------------------
__global__ void viterbi_kernel(const float* __restrict__ feats,
                               const float* __restrict__ trans,
                               float* __restrict__ out,
                               int write_scores, int write_paths, int path_off) {
    const int b = blockIdx.x;
    const int c = threadIdx.x;
    __shared__ unsigned char bp[TT][CC];

    float tr[CC];
#pragma unroll
    for (int p = 0; p < CC; p++) tr[p] = trans[c * CC + p];

    float fv = (c == START_TAG) ? 0.f : -10000.f;
    const float* f = feats + (size_t)b * TT * CC;

    for (int t = 0; t < TT; t++) {
        float best = -3.4e38f;
        int arg = 0;
#pragma unroll
        for (int p = 0; p < CC; p++) {
            float sc = __shfl_sync(0x0000ffffu, fv, p) + tr[p];
            if (sc > best) { best = sc; arg = p; }
        }
        bp[t][c] = (unsigned char)arg;
        fv = best + f[t * CC + c];
    }

    float term = fv + trans[STOP_TAG * CC + c];
    float bv = term;
    int bi = c;
#pragma unroll
    for (int o = 8; o; o >>= 1) {
        float ov = __shfl_down_sync(0x0000ffffu, bv, o);
        int oi = __shfl_down_sync(0x0000ffffu, bi, o);
        if (ov > bv || (ov == bv && oi < bi)) { bv = ov; bi = oi; }
    }
    bv = __shfl_sync(0x0000ffffu, bv, 0);
    bi = __shfl_sync(0x0000ffffu, bi, 0);

    if (c == 0) {
        if (write_scores) out[b] = bv;
        if (write_paths) {
            int tag = bi;
            for (int t = TT - 1; t >= 0; t--) {
                out[path_off + b * TT + t] = (float)tag;
                tag = bp[t][tag];
            }
        }
    }
}

// ---------------- launch -----------------------------------------------------------
extern "C" void kernel_launch(void* const* d_in, const int* in_sizes, int n_in,
                              void* d_out, int out_size) {
    const int*   sent    = (const int*)  d_in[0];
    const float* emb     = (const float*)d_in[1];
    const float* wih0    = (const float*)d_in[2];
    const float* whh0    = (const float*)d_in[3];
    const float* bih0    = (const float*)d_in[4];
    const float* bhh0    = (const float*)d_in[5];
    const float* wih1    = (const float*)d_in[6];
    const float* whh1    = (const float*)d_in[7];
    const float* bih1    = (const float*)d_in[8];
    const float* bhh1    = (const float*)d_in[9];
    const float* linw    = (const float*)d_in[10];
    const float* linb    = (const float*)d_in[11];
    const float* trans   = (const float*)d_in[12];
    const float* h0      = (const float*)d_in[13];
    const float* c0      = (const float*)d_in[14];

    float *pX0, *pG, *pH0, *pH1, *pfe, *phb;
    __nv_bfloat16 *pAs, *pWs;
    cudaGetSymbolAddress((void**)&pX0, g_X0);
    cudaGetSymbolAddress((void**)&pG,  g_G);
    cudaGetSymbolAddress((void**)&pH0, g_H0);
    cudaGetSymbolAddress((void**)&pH1, g_H1);
    cudaGetSymbolAddress((void**)&pfe, g_feats);
    cudaGetSymbolAddress((void**)&phb, g_hbuf);
    cudaGetSymbolAddress((void**)&pAs, g_As);
    cudaGetSymbolAddress((void**)&pWs, g_Ws);

    cudaFuncSetAttribute(gemm_mma, cudaFuncAttributeMaxDynamicSharedMemorySize,
                         GEMM_SMEM);
    cudaFuncSetAttribute(lstm_layer, cudaFuncAttributeMaxDynamicSharedMemorySize,
                         LSTM_SMEM);

    // 1) embedding gather
    embed_kernel<<<MROWS, 128>>>(sent, emb, pX0);

    // 2) layer-0: split + pipelined tensor GEMM (K6 = 3072)
    {
        long long tA = (long long)MROWS * EE;
        long long tW = (long long)NG * EE;
        splitA_kernel<<<(unsigned)((tA + 255) / 256), 256>>>(pX0, pAs, EE, tA);
        splitW_kernel<<<(unsigned)((tW + 255) / 256), 256>>>(wih0, pWs, EE, tW);
        gemm_mma<<<dim3(NG / BN, MROWS / BM), 256, GEMM_SMEM>>>(
            pAs, pWs, bih0, bhh0, pG, 6 * EE);
    }

    // 3) layer-0 recurrence
    lstm_layer<<<dim3(64, 2), 128, LSTM_SMEM>>>(pG, whh0, h0, c0, phb, pH0);

    // 4) layer-1: split + pipelined tensor GEMM (K6 = 6144)
    {
        long long tA = (long long)MROWS * HH;
        long long tW = (long long)NG * HH;
        splitA_kernel<<<(unsigned)((tA + 255) / 256), 256>>>(pH0, pAs, HH, tA);
        splitW_kernel<<<(unsigned)((tW + 255) / 256), 256>>>(wih1, pWs, HH, tW);
        gemm_mma<<<dim3(NG / BN, MROWS / BM), 256, GEMM_SMEM>>>(
            pAs, pWs, bih1, bhh1, pG, 6 * HH);
    }

    // 5) layer-1 recurrence
    lstm_layer<<<dim3(64, 2), 128, LSTM_SMEM>>>(pG, whh1,
                                                h0 + 2 * BB * HD, c0 + 2 * BB * HD,
                                                phb, pH1);

    // 6) linear -> feats
    linear_feats<<<(MROWS * 32 + 255) / 256, 256>>>(pH1, linw, linb, pfe);

    // 7) Viterbi decode + output write
    float* out = (float*)d_out;
    int write_scores, write_paths, path_off;
    if (out_size >= BB + BB * TT) { write_scores = 1; write_paths = 1; path_off = BB; }
    else if (out_size == BB * TT) { write_scores = 0; write_paths = 1; path_off = 0; }
    else                          { write_scores = 1; write_paths = 0; path_off = 0; }
    viterbi_kernel<<<BB, CC>>>(pfe, trans, out, write_scores, write_paths, path_off);
}

// round 8
// speedup vs baseline: 1.0187x; 1.0187x over previous
#include <cuda_runtime.h>
#include <cuda_bf16.h>
#include <math.h>
#include <stdint.h>

// Problem dims
#define TT 512
#define BB 64
#define EE 512
#define HD 512
#define HH 1024
#define CC 16
#define START_TAG 14
#define STOP_TAG 15
#define NG 4096          // 2 dirs * 4 gates * HD
#define MROWS (TT*BB)    // 32768

// GEMM tiling
#define BM 128
#define BN 128
#define BK 32
#define NSTAGE 3
#define PADH 40
#define SA_BYTES (BM * PADH * 2)             // 10240
#define SB_BYTES (BN * PADH * 2)             // 10240
#define GEMM_SMEM_USED (NSTAGE * (SA_BYTES + SB_BYTES))   // 61440
#define NT (NG / BN)                         // 32 n-tiles
#define NMT (MROWS / BM)                     // 256 m-tiles (2 timesteps each)

// LSTM smem layout
#define LS_WS 0                              // float Ws[512][32]   = 65536 B
#define LS_HS 65536                          // float Hs[2][16][68] = 8704 B
#define LS_GS (65536 + 8704)                 // float gs[4][64][8]  = 8192 B
#define FUSED_SMEM (LS_GS + 8192)            // 82432 B (>= GEMM_SMEM_USED)

// ---------------- scratch ------------------------------------------------------
__device__ float g_X0[(size_t)MROWS * EE];
__device__ float g_G [(size_t)MROWS * NG];
__device__ float g_H0[(size_t)MROWS * HH];
__device__ float g_H1[(size_t)MROWS * HH];
__device__ __nv_bfloat16 g_As[(size_t)MROWS * 6 * HH];
__device__ __nv_bfloat16 g_Ws0[(size_t)NG * 6 * EE];
__device__ __nv_bfloat16 g_Ws1[(size_t)NG * 6 * HH];
__device__ float g_feats[(size_t)BB * TT * CC];
__device__ float g_hbuf[2 * 2 * BB * HD];
__device__ unsigned int g_tilecnt[NMT];

__device__ unsigned int g_bar_count;
__device__ unsigned int g_bar_gen;

__device__ __forceinline__ void grid_barrier(int nblk) {
    __syncthreads();
    if (threadIdx.x == 0) {
        __threadfence();
        unsigned int gen = *(volatile unsigned int*)&g_bar_gen;
        if (atomicAdd(&g_bar_count, 1u) == (unsigned)(nblk - 1)) {
            g_bar_count = 0;
            __threadfence();
            atomicAdd(&g_bar_gen, 1u);
        } else {
            unsigned int cur;
            do {
                asm volatile("ld.acquire.gpu.u32 %0, [%1];"
                             : "=r"(cur) : "l"(&g_bar_gen));
            } while (cur == gen);
        }
    }
    __syncthreads();
}

__device__ __forceinline__ uint32_t smem_u32(const void* p) {
    uint32_t a;
    asm("{ .reg .u64 t; cvta.to.shared.u64 t, %1; cvt.u32.u64 %0, t; }"
        : "=r"(a) : "l"(p));
    return a;
}

// ---------------- embedding gather ---------------------------------------------
__global__ void embed_kernel(const int* __restrict__ sent,
                             const float* __restrict__ emb,
                             float* __restrict__ X0) {
    int m = blockIdx.x;
    int t = m >> 6;
    int b = m & 63;
    int tok = sent[b * TT + t];
    const float4* src = reinterpret_cast<const float4*>(emb + (size_t)tok * EE);
    float4* dst = reinterpret_cast<float4*>(X0 + (size_t)m * EE);
    dst[threadIdx.x] = src[threadIdx.x];
}

// ---------------- fp32 -> 3-term bf16 split (K-concatenated, exact) ------------
__global__ void splitA_kernel(const float* __restrict__ X,
                              __nv_bfloat16* __restrict__ Y,
                              int K, long long total) {
    long long idx = (long long)blockIdx.x * blockDim.x + threadIdx.x;
    if (idx >= total) return;
    int m = (int)(idx / K);
    int k = (int)(idx % K);
    float a = X[idx];
    __nv_bfloat16 b0 = __float2bfloat16(a);
    float r = a - __bfloat162float(b0);
    __nv_bfloat16 b1 = __float2bfloat16(r);
    float r2 = r - __bfloat162float(b1);
    __nv_bfloat16 b2 = __float2bfloat16(r2);
    __nv_bfloat16* base = Y + (size_t)m * 6 * K + k;
    base[0 * K] = b0; base[1 * K] = b0; base[2 * K] = b1;
    base[3 * K] = b0; base[4 * K] = b1; base[5 * K] = b2;
}
__global__ void splitW_kernel(const float* __restrict__ X,
                              __nv_bfloat16* __restrict__ Y,
                              int K, long long total) {
    long long idx = (long long)blockIdx.x * blockDim.x + threadIdx.x;
    if (idx >= total) return;
    int m = (int)(idx / K);
    int k = (int)(idx % K);
    float a = X[idx];
    __nv_bfloat16 b0 = __float2bfloat16(a);
    float r = a - __bfloat162float(b0);
    __nv_bfloat16 b1 = __float2bfloat16(r);
    float r2 = r - __bfloat162float(b1);
    __nv_bfloat16 b2 = __float2bfloat16(r2);
    __nv_bfloat16* base = Y + (size_t)m * 6 * K + k;
    base[0 * K] = b0; base[1 * K] = b1; base[2 * K] = b0;
    base[3 * K] = b2; base[4 * K] = b1; base[5 * K] = b0;
}

// ---------------- mma / cp.async helpers ----------------------------------------
__device__ __forceinline__ void ldsm4(uint32_t addr, uint32_t r[4]) {
    asm volatile("ldmatrix.sync.aligned.m8n8.x4.shared.b16 {%0,%1,%2,%3}, [%4];"
                 : "=r"(r[0]), "=r"(r[1]), "=r"(r[2]), "=r"(r[3]) : "r"(addr));
}
__device__ __forceinline__ void mma16816(float c[4], const uint32_t a[4],
                                         const uint32_t b[2]) {
    asm volatile(
        "mma.sync.aligned.m16n8k16.row.col.f32.bf16.bf16.f32 "
        "{%0,%1,%2,%3}, {%4,%5,%6,%7}, {%8,%9}, {%0,%1,%2,%3};"
        : "+f"(c[0]), "+f"(c[1]), "+f"(c[2]), "+f"(c[3])
        : "r"(a[0]), "r"(a[1]), "r"(a[2]), "r"(a[3]), "r"(b[0]), "r"(b[1]));
}
__device__ __forceinline__ void cp16(uint32_t dst, const void* src) {
    asm volatile("cp.async.cg.shared.global [%0], [%1], 16;" :: "r"(dst), "l"(src));
}
__device__ __forceinline__ void cp_commit() {
    asm volatile("cp.async.commit_group;");
}
template <int N>
__device__ __forceinline__ void cp_wait() {
    asm volatile("cp.async.wait_group %0;" :: "n"(N));
}

// ================= fused layer: GEMM workers + persistent LSTM ==================
// blocks 0..127: LSTM (dir = bid>>6, u0 = (bid&63)*8), 256 thr (128 active)
// blocks 128.. : GEMM tile workers; mtile order both-ends-first; per-mtile counter.
__global__ void __launch_bounds__(256, 2)
fused_layer(const __nv_bfloat16* __restrict__ A,   // [M][K6] split
            const __nv_bfloat16* __restrict__ Wsp, // [NG][K6] split
            const float* __restrict__ b1,
            const float* __restrict__ b2,
            float* __restrict__ G,                 // [MROWS][NG]
            const float* __restrict__ Whh,         // [2][2048][HD]
            const float* __restrict__ h0,
            const float* __restrict__ c0,
            float* __restrict__ hbuf,
            float* __restrict__ Hcat,
            int K6,
            unsigned int* __restrict__ cnt) {
    extern __shared__ char dsm[];
    const int tid = threadIdx.x;

    if (blockIdx.x >= 128) {
        // ======================= GEMM worker ====================================
        const int gb = blockIdx.x - 128;
        const int ntile = gb & (NT - 1);
        const int pseq = gb >> 5;
        const int mtile = (pseq & 1) ? (NMT - 1 - (pseq >> 1)) : (pseq >> 1);
        const int m0 = mtile * BM;
        const int n0 = ntile * BN;

        const uint32_t sAb = smem_u32(dsm);
        const uint32_t sBb = sAb + NSTAGE * SA_BYTES;
        const int lane = tid & 31;
        const int wid = tid >> 5;
        const int warpm = wid >> 2;
        const int warpn = wid & 3;

        const int rowoff = ((lane >> 3) & 1) * 8 + (lane & 7);
        const int koffA  = (lane >> 4) * 8;
        const int noff   = ((lane >> 4) << 3) + (lane & 7);
        const int koffB  = ((lane >> 3) & 1) * 8;

        float acc[4][4][4];
#pragma unroll
        for (int i = 0; i < 4; i++)
#pragma unroll
            for (int j = 0; j < 4; j++)
#pragma unroll
                for (int q = 0; q < 4; q++) acc[i][j][q] = 0.f;

        auto issue = [&](int stage, int kt) {
            const int kb = kt * BK;
            const uint32_t sa = sAb + stage * SA_BYTES;
            const uint32_t sb = sBb + stage * SB_BYTES;
#pragma unroll
            for (int q = 0; q < 2; q++) {
                int id = tid + q * 256;
                int r = id >> 2, c4 = id & 3;
                cp16(sa + (uint32_t)(r * PADH + c4 * 8) * 2,
                     A + (size_t)(m0 + r) * K6 + kb + c4 * 8);
            }
#pragma unroll
            for (int q = 0; q < 2; q++) {
                int id = tid + q * 256;
                int r = id >> 2, c4 = id & 3;
                cp16(sb + (uint32_t)(r * PADH + c4 * 8) * 2,
                     Wsp + (size_t)(n0 + r) * K6 + kb + c4 * 8);
            }
        };

        issue(0, 0); cp_commit();
        issue(1, 1); cp_commit();

        const int nkt = K6 / BK;
        int stage = 0;
        for (int kt = 0; kt < nkt; kt++) {
            cp_wait<1>();
            __syncthreads();
            if (kt + 2 < nkt) {
                int ns = stage + 2; if (ns >= NSTAGE) ns -= NSTAGE;
                issue(ns, kt + 2);
            }
            cp_commit();

            const uint32_t sa = sAb + stage * SA_BYTES;
            const uint32_t sb = sBb + stage * SB_BYTES;
#pragma unroll
            for (int ks = 0; ks < 2; ks++) {
                uint32_t af[4][4];
                uint32_t bf[4][2];
#pragma unroll
                for (int mf = 0; mf < 4; mf++) {
                    int mrow = warpm * 64 + mf * 16 + rowoff;
                    ldsm4(sa + (uint32_t)(mrow * PADH + ks * 16 + koffA) * 2, af[mf]);
                }
#pragma unroll
                for (int p = 0; p < 2; p++) {
                    uint32_t rr[4];
                    int nrow = warpn * 32 + p * 16 + noff;
                    ldsm4(sb + (uint32_t)(nrow * PADH + ks * 16 + koffB) * 2, rr);
                    bf[2 * p][0] = rr[0];     bf[2 * p][1] = rr[1];
                    bf[2 * p + 1][0] = rr[2]; bf[2 * p + 1][1] = rr[3];
                }
#pragma unroll
                for (int mf = 0; mf < 4; mf++)
#pragma unroll
                    for (int nf = 0; nf < 4; nf++)
                        mma16816(acc[mf][nf], af[mf], bf[nf]);
            }
            if (++stage == NSTAGE) stage = 0;
        }

        // epilogue
#pragma unroll
        for (int nf = 0; nf < 4; nf++) {
            const int col = n0 + warpn * 32 + nf * 8 + (lane & 3) * 2;
            const float bx = b1[col] + b2[col];
            const float by = b1[col + 1] + b2[col + 1];
#pragma unroll
            for (int mf = 0; mf < 4; mf++) {
                const int row = m0 + warpm * 64 + mf * 16 + (lane >> 2);
                float2 v0 = make_float2(acc[mf][nf][0] + bx, acc[mf][nf][1] + by);
                float2 v1 = make_float2(acc[mf][nf][2] + bx, acc[mf][nf][3] + by);
                *reinterpret_cast<float2*>(G + (size_t)row * NG + col) = v0;
                *reinterpret_cast<float2*>(G + (size_t)(row + 8) * NG + col) = v1;
            }
        }
        __threadfence();
        __syncthreads();
        if (tid == 0) atomicAdd(&cnt[mtile], 1u);
        return;
    }

    // ========================= LSTM block =======================================
    float (*Ws)[32]     = reinterpret_cast<float(*)[32]>(dsm + LS_WS);
    float (*Hs)[16][68] = reinterpret_cast<float(*)[16][68]>(dsm + LS_HS);
    float (*gs)[64][8]  = reinterpret_cast<float(*)[64][8]>(dsm + LS_GS);

    const int bid = blockIdx.x;
    const int dir = bid >> 6;
    const int u0 = (bid & 63) * 8;
    const bool act = tid < 128;
    const float* W = Whh + (size_t)dir * 2048 * HD;

    const int lcc = tid & 31;
    const int lgate = lcc >> 3;
    const int lu = u0 + (lcc & 7);
    const int lkq = (tid & 127) >> 5;
    const int lb = tid & 63;
    const int hkq0 = (tid & 127) >> 6;

    if (act) {
        for (int kt = 0; kt < HD; kt += 16) {
            float4 v = *reinterpret_cast<const float4*>(
                &W[(size_t)(lgate * HD + lu) * HD + kt + lkq * 4]);
            Ws[kt + lkq * 4 + 0][lcc] = v.x; Ws[kt + lkq * 4 + 1][lcc] = v.y;
            Ws[kt + lkq * 4 + 2][lcc] = v.z; Ws[kt + lkq * 4 + 3][lcc] = v.w;
        }
    }

    float cr[4];
    if (act) {
#pragma unroll
        for (int i = 0; i < 4; i++) {
            int p = tid + i * 128;
            int b = p >> 3, ul = p & 7;
            size_t idx = (size_t)dir * BB * HD + b * HD + u0 + ul;
            cr[i] = c0[idx];
            hbuf[idx] = h0[idx];
        }
    }
    grid_barrier(128);

    const int b0  = (tid >> 3) * 4;          // valid for act
    const int cg0 = (tid & 7) * 4;
    const int g0  = cg0 >> 3;
    const int ul0 = cg0 & 7;

    for (int s = 0; s < TT; s++) {
        const int t = dir ? (TT - 1 - s) : s;
        const float* h = hbuf + (size_t)(s & 1) * 2 * BB * HD
                              + (size_t)dir * BB * HD;
        float* ho = hbuf + (size_t)((s + 1) & 1) * 2 * BB * HD
                         + (size_t)dir * BB * HD;

        if (act) {
#pragma unroll
            for (int itq = 0; itq < 2; itq++) {
                int kq = hkq0 + itq * 2;
                float4 v = *reinterpret_cast<const float4*>(&h[lb * HD + kq * 4]);
                Hs[0][kq * 4 + 0][lb] = v.x; Hs[0][kq * 4 + 1][lb] = v.y;
                Hs[0][kq * 4 + 2][lb] = v.z; Hs[0][kq * 4 + 3][lb] = v.w;
            }
        }
        __syncthreads();

        float acc[4][4];
#pragma unroll
        for (int i = 0; i < 4; i++)
#pragma unroll
            for (int j = 0; j < 4; j++) acc[i][j] = 0.f;

        for (int kt16 = 0; kt16 < 32; kt16++) {
            const int cur = kt16 & 1;
            if (act) {
                float4 pv0, pv1;
                const bool pf = (kt16 < 31);
                if (pf) {
                    const int kb = (kt16 + 1) * 16;
                    pv0 = *reinterpret_cast<const float4*>(&h[lb * HD + kb + hkq0 * 4]);
                    pv1 = *reinterpret_cast<const float4*>(&h[lb * HD + kb + (hkq0 + 2) * 4]);
                }
#pragma unroll
                for (int k = 0; k < 16; k++) {
                    float4 hv = *reinterpret_cast<const float4*>(&Hs[cur][k][b0]);
                    float4 wv = *reinterpret_cast<const float4*>(&Ws[kt16 * 16 + k][cg0]);
                    float ar[4] = {hv.x, hv.y, hv.z, hv.w};
                    float br[4] = {wv.x, wv.y, wv.z, wv.w};
#pragma unroll
                    for (int i = 0; i < 4; i++)
#pragma unroll
                        for (int j = 0; j < 4; j++) acc[i][j] += ar[i] * br[j];
                }
                if (pf) {
                    const int nb = cur ^ 1;
                    Hs[nb][hkq0 * 4 + 0][lb] = pv0.x; Hs[nb][hkq0 * 4 + 1][lb] = pv0.y;
                    Hs[nb][hkq0 * 4 + 2][lb] = pv0.z; Hs[nb][hkq0 * 4 + 3][lb] = pv0.w;
                    Hs[nb][(hkq0 + 2) * 4 + 0][lb] = pv1.x;
                    Hs[nb][(hkq0 + 2) * 4 + 1][lb] = pv1.y;
                    Hs[nb][(hkq0 + 2) * 4 + 2][lb] = pv1.z;
                    Hs[nb][(hkq0 + 2) * 4 + 3][lb] = pv1.w;
                }
            }
            __syncthreads();
        }

        // wait until this timestep's G m-tile is complete (32 n-tiles)
        if (tid == 0) {
            const int mt = t >> 1;
            unsigned int v;
            do {
                asm volatile("ld.acquire.gpu.u32 %0, [%1];"
                             : "=r"(v) : "l"(&cnt[mt]));
            } while (v < (unsigned)NT);
        }
        __syncthreads();

        if (act) {
            const int row0 = t * BB;
#pragma unroll
            for (int i = 0; i < 4; i++) {
                int b = b0 + i;
                float4 gv = *reinterpret_cast<const float4*>(
                    &G[(size_t)(row0 + b) * NG + dir * 2048 + g0 * HD + u0 + ul0]);
                gs[g0][b][ul0 + 0] = acc[i][0] + gv.x;
                gs[g0][b][ul0 + 1] = acc[i][1] + gv.y;
                gs[g0][b][ul0 + 2] = acc[i][2] + gv.z;
                gs[g0][b][ul0 + 3] = acc[i][3] + gv.w;
            }
        }
        __syncthreads();

        if (act) {
#pragma unroll
            for (int i = 0; i < 4; i++) {
                int p = tid + i * 128;
                int b = p >> 3;
                int ul = p & 7;
                int u = u0 + ul;
                float ig = gs[0][b][ul];
                float fg = gs[1][b][ul];
                float gg = gs[2][b][ul];
                float og = gs[3][b][ul];
                float si = 1.f / (1.f + expf(-ig));
                float sf = 1.f / (1.f + expf(-fg));
                float so = 1.f / (1.f + expf(-og));
                float cn = sf * cr[i] + si * tanhf(gg);
                float hn = so * tanhf(cn);
                cr[i] = cn;
                ho[b * HD + u] = hn;
                Hcat[(size_t)t * BB * HH + b * HH + dir * HD + u] = hn;
            }
        }
        grid_barrier(128);
    }
}

// ---------------- final linear ---------------------------------------------------
__global__ void linear_feats(const float* __restrict__ H1,
                             const float* __restrict__ lw,
                             const float* __restrict__ lb,
                             float* __restrict__ feats) {
    int warp = (blockIdx.x * blockDim.x + threadIdx.x) >> 5;
    int lane = threadIdx.x & 31;
    if (warp >= MROWS) return;
    const float* hrow = H1 + (size_t)warp * HH;
    float acc[CC];
#pragma unroll
    for (int c = 0; c < CC; c++) acc[c] = 0.f;
    for (int k = lane; k < HH; k += 32) {
        float hv = hrow[k];
#pragma unroll
        for (int c = 0; c < CC; c++) acc[c] += hv * lw[c * HH + k];
    }
#pragma unroll
    for (int c = 0; c < CC; c++) {
        float v = acc[c];
#pragma unroll
        for (int o = 16; o; o >>= 1) v += __shfl_down_sync(0xffffffffu, v, o);
        if (lane == 0) {
            int t = warp >> 6, b = warp & 63;
            feats[((size_t)b * TT + t) * CC + c] = v + lb[c];
        }
    }
}

// ---------------- Viterbi decode --------------------------------------------------
__global__ void viterbi_kernel(const float* __restrict__ feats,
                               const float* __restrict__ trans,
                               float* __restrict__ out,
                               int write_scores, int write_paths, int path_off) {
    const int b = blockIdx.x;
    const int c = threadIdx.x;
    __shared__ unsigned char bp[TT][CC];

    float tr[CC];
#pragma unroll
    for (int p = 0; p < CC; p++) tr[p] = trans[c * CC + p];

    float fv = (c == START_TAG) ? 0.f : -10000.f;
    const float* f = feats + (size_t)b * TT * CC;

    for (int t = 0; t < TT; t++) {
        float best = -3.4e38f;
        int arg = 0;
#pragma unroll
        for (int p = 0; p < CC; p++) {
            float sc = __shfl_sync(0x0000ffffu, fv, p) + tr[p];
            if (sc > best) { best = sc; arg = p; }
        }
        bp[t][c] = (unsigned char)arg;
        fv = best + f[t * CC + c];
    }

    float term = fv + trans[STOP_TAG * CC + c];
    float bv = term;
    int bi = c;
#pragma unroll
    for (int o = 8; o; o >>= 1) {
        float ov = __shfl_down_sync(0x0000ffffu, bv, o);
        int oi = __shfl_down_sync(0x0000ffffu, bi, o);
        if (ov > bv || (ov == bv && oi < bi)) { bv = ov; bi = oi; }
    }
    bv = __shfl_sync(0x0000ffffu, bv, 0);
    bi = __shfl_sync(0x0000ffffu, bi, 0);

    if (c == 0) {
        if (write_scores) out[b] = bv;
        if (write_paths) {
            int tag = bi;
            for (int t = TT - 1; t >= 0; t--) {
                out[path_off + b * TT + t] = (float)tag;
                tag = bp[t][tag];
            }
        }
    }
}

// ---------------- launch -----------------------------------------------------------
extern "C" void kernel_launch(void* const* d_in, const int* in_sizes, int n_in,
                              void* d_out, int out_size) {
    const int*   sent    = (const int*)  d_in[0];
    const float* emb     = (const float*)d_in[1];
    const float* wih0    = (const float*)d_in[2];
    const float* whh0    = (const float*)d_in[3];
    const float* bih0    = (const float*)d_in[4];
    const float* bhh0    = (const float*)d_in[5];
    const float* wih1    = (const float*)d_in[6];
    const float* whh1    = (const float*)d_in[7];
    const float* bih1    = (const float*)d_in[8];
    const float* bhh1    = (const float*)d_in[9];
    const float* linw    = (const float*)d_in[10];
    const float* linb    = (const float*)d_in[11];
    const float* trans   = (const float*)d_in[12];
    const float* h0      = (const float*)d_in[13];
    const float* c0      = (const float*)d_in[14];

    float *pX0, *pG, *pH0, *pH1, *pfe, *phb;
    __nv_bfloat16 *pAs, *pWs0, *pWs1;
    unsigned int* pcnt;
    cudaGetSymbolAddress((void**)&pX0, g_X0);
    cudaGetSymbolAddress((void**)&pG,  g_G);
    cudaGetSymbolAddress((void**)&pH0, g_H0);
    cudaGetSymbolAddress((void**)&pH1, g_H1);
    cudaGetSymbolAddress((void**)&pfe, g_feats);
    cudaGetSymbolAddress((void**)&phb, g_hbuf);
    cudaGetSymbolAddress((void**)&pAs, g_As);
    cudaGetSymbolAddress((void**)&pWs0, g_Ws0);
    cudaGetSymbolAddress((void**)&pWs1, g_Ws1);
    cudaGetSymbolAddress((void**)&pcnt, g_tilecnt);

    cudaFuncSetAttribute(fused_layer, cudaFuncAttributeMaxDynamicSharedMemorySize,
                         FUSED_SMEM);

    const int FUSED_BLOCKS = 128 + NMT * NT;   // 128 + 8192

    // 1) embedding gather + weight splits (weights independent of layer outputs)
    embed_kernel<<<MROWS, 128>>>(sent, emb, pX0);
    {
        long long tW0 = (long long)NG * EE;
        long long tW1 = (long long)NG * HH;
        splitW_kernel<<<(unsigned)((tW0 + 255) / 256), 256>>>(wih0, pWs0, EE, tW0);
        splitW_kernel<<<(unsigned)((tW1 + 255) / 256), 256>>>(wih1, pWs1, HH, tW1);
    }

    // 2) layer-0: split X0, then fused GEMM+LSTM
    {
        long long tA = (long long)MROWS * EE;
        splitA_kernel<<<(unsigned)((tA + 255) / 256), 256>>>(pX0, pAs, EE, tA);
        cudaMemsetAsync(pcnt, 0, NMT * sizeof(unsigned int));
        fused_layer<<<FUSED_BLOCKS, 256, FUSED_SMEM>>>(
            pAs, pWs0, bih0, bhh0, pG, whh0, h0, c0, phb, pH0, 6 * EE, pcnt);
    }

    // 3) layer-1: split H0, then fused GEMM+LSTM
    {
        long long tA = (long long)MROWS * HH;
        splitA_kernel<<<(unsigned)((tA + 255) / 256), 256>>>(pH0, pAs, HH, tA);
        cudaMemsetAsync(pcnt, 0, NMT * sizeof(unsigned int));
        fused_layer<<<FUSED_BLOCKS, 256, FUSED_SMEM>>>(
            pAs, pWs1, bih1, bhh1, pG, whh1,
            h0 + 2 * BB * HD, c0 + 2 * BB * HD, phb, pH1, 6 * HH, pcnt);
    }

    // 4) linear -> feats
    linear_feats<<<(MROWS * 32 + 255) / 256, 256>>>(pH1, linw, linb, pfe);

    // 5) Viterbi decode + output write
    float* out = (float*)d_out;
    int write_scores, write_paths, path_off;
    if (out_size >= BB + BB * TT) { write_scores = 1; write_paths = 1; path_off = BB; }
    else if (out_size == BB * TT) { write_scores = 0; write_paths = 1; path_off = 0; }
    else                          { write_scores = 1; write_paths = 0; path_off = 0; }
    viterbi_kernel<<<BB, CC>>>(pfe, trans, out, write_scores, write_paths, path_off);
}

// round 9
// speedup vs baseline: 1.1550x; 1.1338x over previous
#include <cuda_runtime.h>
#include <cuda_bf16.h>
#include <math.h>
#include <stdint.h>

// Problem dims
#define TT 512
#define BB 64
#define EE 512
#define HD 512
#define HH 1024
#define CC 16
#define START_TAG 14
#define STOP_TAG 15
#define NG 4096          // 2 dirs * 4 gates * HD
#define MROWS (TT*BB)    // 32768

// ---------------- scratch ------------------------------------------------------
__device__ float g_X0[(size_t)MROWS * EE];
__device__ float g_G [(size_t)MROWS * NG];
__device__ float g_H0[(size_t)MROWS * HH];
__device__ float g_H1[(size_t)MROWS * HH];
__device__ __nv_bfloat16 g_As[(size_t)MROWS * 6 * HH];
__device__ __nv_bfloat16 g_Ws[(size_t)NG * 6 * HH];
__device__ float g_feats[(size_t)BB * TT * CC];
__device__ float g_hbuf[2 * 2 * BB * HD];

__device__ unsigned int g_bar_count;
__device__ unsigned int g_bar_gen;

__device__ __forceinline__ void grid_barrier(int nblk) {
    __syncthreads();
    if (threadIdx.x == 0) {
        __threadfence();
        unsigned int gen = *(volatile unsigned int*)&g_bar_gen;
        if (atomicAdd(&g_bar_count, 1u) == (unsigned)(nblk - 1)) {
            g_bar_count = 0;
            __threadfence();
            atomicAdd(&g_bar_gen, 1u);
        } else {
            unsigned int cur;
            do {
                asm volatile("ld.acquire.gpu.u32 %0, [%1];"
                             : "=r"(cur) : "l"(&g_bar_gen));
            } while (cur == gen);
        }
    }
    __syncthreads();
}

__device__ __forceinline__ uint32_t smem_u32(const void* p) {
    uint32_t a;
    asm("{ .reg .u64 t; cvta.to.shared.u64 t, %1; cvt.u32.u64 %0, t; }"
        : "=r"(a) : "l"(p));
    return a;
}

// ---------------- embedding gather ---------------------------------------------
__global__ void embed_kernel(const int* __restrict__ sent,
                             const float* __restrict__ emb,
                             float* __restrict__ X0) {
    int m = blockIdx.x;
    int t = m >> 6;
    int b = m & 63;
    int tok = sent[b * TT + t];
    const float4* src = reinterpret_cast<const float4*>(emb + (size_t)tok * EE);
    float4* dst = reinterpret_cast<float4*>(X0 + (size_t)m * EE);
    dst[threadIdx.x] = src[threadIdx.x];
}

// ---------------- fp32 -> 3-term bf16 split (K-concatenated, exact) ------------
__global__ void splitA_kernel(const float* __restrict__ X,
                              __nv_bfloat16* __restrict__ Y,
                              int K, long long total) {
    long long idx = (long long)blockIdx.x * blockDim.x + threadIdx.x;
    if (idx >= total) return;
    int m = (int)(idx / K);
    int k = (int)(idx % K);
    float a = X[idx];
    __nv_bfloat16 b0 = __float2bfloat16(a);
    float r = a - __bfloat162float(b0);
    __nv_bfloat16 b1 = __float2bfloat16(r);
    float r2 = r - __bfloat162float(b1);
    __nv_bfloat16 b2 = __float2bfloat16(r2);
    __nv_bfloat16* base = Y + (size_t)m * 6 * K + k;
    base[0 * K] = b0; base[1 * K] = b0; base[2 * K] = b1;
    base[3 * K] = b0; base[4 * K] = b1; base[5 * K] = b2;
}
__global__ void splitW_kernel(const float* __restrict__ X,
                              __nv_bfloat16* __restrict__ Y,
                              int K, long long total) {
    long long idx = (long long)blockIdx.x * blockDim.x + threadIdx.x;
    if (idx >= total) return;
    int m = (int)(idx / K);
    int k = (int)(idx % K);
    float a = X[idx];
    __nv_bfloat16 b0 = __float2bfloat16(a);
    float r = a - __bfloat162float(b0);
    __nv_bfloat16 b1 = __float2bfloat16(r);
    float r2 = r - __bfloat162float(b1);
    __nv_bfloat16 b2 = __float2bfloat16(r2);
    __nv_bfloat16* base = Y + (size_t)m * 6 * K + k;
    base[0 * K] = b0; base[1 * K] = b1; base[2 * K] = b0;
    base[3 * K] = b2; base[4 * K] = b1; base[5 * K] = b0;
}

// ================= pipelined warp-mma bf16 GEMM (BK=64, BN=256) =================
#define BM 128
#define BN 256
#define BK 64
#define NSTAGE 3
#define PADH 72                               // 64-half row + 8 pad (144B, cf-free)
#define SA_BYTES (BM * PADH * 2)              // 18432
#define SB_BYTES (BN * PADH * 2)              // 36864
#define GEMM_SMEM (NSTAGE * (SA_BYTES + SB_BYTES))   // 165888 -> 1 CTA/SM

__device__ __forceinline__ void ldsm4(uint32_t addr, uint32_t r[4]) {
    asm volatile("ldmatrix.sync.aligned.m8n8.x4.shared.b16 {%0,%1,%2,%3}, [%4];"
                 : "=r"(r[0]), "=r"(r[1]), "=r"(r[2]), "=r"(r[3]) : "r"(addr));
}
__device__ __forceinline__ void mma16816(float c[4], const uint32_t a[4],
                                         const uint32_t b[2]) {
    asm volatile(
        "mma.sync.aligned.m16n8k16.row.col.f32.bf16.bf16.f32 "
        "{%0,%1,%2,%3}, {%4,%5,%6,%7}, {%8,%9}, {%0,%1,%2,%3};"
        : "+f"(c[0]), "+f"(c[1]), "+f"(c[2]), "+f"(c[3])
        : "r"(a[0]), "r"(a[1]), "r"(a[2]), "r"(a[3]), "r"(b[0]), "r"(b[1]));
}
__device__ __forceinline__ void cp16(uint32_t dst, const void* src) {
    asm volatile("cp.async.cg.shared.global [%0], [%1], 16;" :: "r"(dst), "l"(src));
}
__device__ __forceinline__ void cp_commit() {
    asm volatile("cp.async.commit_group;");
}
template <int N>
__device__ __forceinline__ void cp_wait() {
    asm volatile("cp.async.wait_group %0;" :: "n"(N));
}

__global__ void __launch_bounds__(256, 1)
gemm_mma(const __nv_bfloat16* __restrict__ A,
         const __nv_bfloat16* __restrict__ W,
         const float* __restrict__ b1,
         const float* __restrict__ b2,
         float* __restrict__ C,
         int K6) {
    extern __shared__ char dsm[];
    const uint32_t sAb = smem_u32(dsm);
    const uint32_t sBb = sAb + NSTAGE * SA_BYTES;

    const int tid = threadIdx.x;
    const int lane = tid & 31;
    const int wid = tid >> 5;
    const int warpm = wid >> 2;     // 0..1 (64 rows)
    const int warpn = wid & 3;      // 0..3 (64 cols)
    const int n0 = blockIdx.x * BN;
    const int m0 = blockIdx.y * BM;

    const int rowoff = ((lane >> 3) & 1) * 8 + (lane & 7);
    const int koffA  = (lane >> 4) * 8;
    const int noff   = ((lane >> 4) << 3) + (lane & 7);
    const int koffB  = ((lane >> 3) & 1) * 8;

    float acc[4][8][4];
#pragma unroll
    for (int i = 0; i < 4; i++)
#pragma unroll
        for (int j = 0; j < 8; j++)
#pragma unroll
            for (int q = 0; q < 4; q++) acc[i][j][q] = 0.f;

    // per ktile: A 128x64 halves = 1024 x16B chunks (4/thread); B 2048 (8/thread)
    auto issue = [&](int stage, int kt) {
        const int kb = kt * BK;
        const uint32_t sa = sAb + stage * SA_BYTES;
        const uint32_t sb = sBb + stage * SB_BYTES;
#pragma unroll
        for (int q = 0; q < 4; q++) {
            int c = tid + q * 256;
            int r = c >> 3, c8 = c & 7;
            cp16(sa + (uint32_t)(r * PADH + c8 * 8) * 2,
                 A + (size_t)(m0 + r) * K6 + kb + c8 * 8);
        }
#pragma unroll
        for (int q = 0; q < 8; q++) {
            int c = tid + q * 256;
            int r = c >> 3, c8 = c & 7;
            cp16(sb + (uint32_t)(r * PADH + c8 * 8) * 2,
                 W + (size_t)(n0 + r) * K6 + kb + c8 * 8);
        }
    };

    issue(0, 0); cp_commit();
    issue(1, 1); cp_commit();

    const int nkt = K6 / BK;
    int stage = 0;
    for (int kt = 0; kt < nkt; kt++) {
        cp_wait<1>();
        __syncthreads();
        if (kt + 2 < nkt) {
            int ns = stage + 2; if (ns >= NSTAGE) ns -= NSTAGE;
            issue(ns, kt + 2);
        }
        cp_commit();

        const uint32_t sa = sAb + stage * SA_BYTES;
        const uint32_t sb = sBb + stage * SB_BYTES;
#pragma unroll
        for (int ks = 0; ks < 4; ks++) {
            uint32_t af[4][4];
            uint32_t bf[8][2];
#pragma unroll
            for (int mf = 0; mf < 4; mf++) {
                int mrow = warpm * 64 + mf * 16 + rowoff;
                ldsm4(sa + (uint32_t)(mrow * PADH + ks * 16 + koffA) * 2, af[mf]);
            }
#pragma unroll
            for (int p = 0; p < 4; p++) {
                uint32_t rr[4];
                int nrow = warpn * 64 + p * 16 + noff;
                ldsm4(sb + (uint32_t)(nrow * PADH + ks * 16 + koffB) * 2, rr);
                bf[2 * p][0] = rr[0];     bf[2 * p][1] = rr[1];
                bf[2 * p + 1][0] = rr[2]; bf[2 * p + 1][1] = rr[3];
            }
#pragma unroll
            for (int mf = 0; mf < 4; mf++)
#pragma unroll
                for (int nf = 0; nf < 8; nf++)
                    mma16816(acc[mf][nf], af[mf], bf[nf]);
        }
        if (++stage == NSTAGE) stage = 0;
    }

    // epilogue: fp32 + biases
#pragma unroll
    for (int nf = 0; nf < 8; nf++) {
        const int col = n0 + warpn * 64 + nf * 8 + (lane & 3) * 2;
        const float bx = b1[col] + b2[col];
        const float by = b1[col + 1] + b2[col + 1];
#pragma unroll
        for (int mf = 0; mf < 4; mf++) {
            const int row = m0 + warpm * 64 + mf * 16 + (lane >> 2);
            float2 v0 = make_float2(acc[mf][nf][0] + bx, acc[mf][nf][1] + by);
            float2 v1 = make_float2(acc[mf][nf][2] + bx, acc[mf][nf][3] + by);
            *reinterpret_cast<float2*>(C + (size_t)row * NG + col) = v0;
            *reinterpret_cast<float2*>(C + (size_t)(row + 8) * NG + col) = v1;
        }
    }
}

// ---------------- persistent bidirectional LSTM layer (k-split x2) --------------
// 128 blocks (dir, 8 units), 256 threads = 2 k-halves x 128.
#define LS_WS  0                              // float Ws[512][32]        = 65536
#define LS_HS  65536                          // float Hs[2][2][16][68]   = 17408
#define LS_RED (65536 + 17408)                // float red[16][128]       = 8192
#define LS_GS  (65536 + 17408 + 8192)         // float gs[4][64][8]       = 8192
#define LSTM_SMEM (LS_GS + 8192)              // 99328

__global__ void __launch_bounds__(256)
lstm_layer(const float* __restrict__ G,
           const float* __restrict__ Whh,
           const float* __restrict__ h0,
           const float* __restrict__ c0,
           float* __restrict__ hbuf,
           float* __restrict__ Hcat) {
    extern __shared__ char dsm[];
    float (*Ws)[32]         = reinterpret_cast<float(*)[32]>(dsm + LS_WS);
    float (*Hs)[2][16][68]  = reinterpret_cast<float(*)[2][16][68]>(dsm + LS_HS);
    float (*red)[128]       = reinterpret_cast<float(*)[128]>(dsm + LS_RED);
    float (*gs)[64][8]      = reinterpret_cast<float(*)[64][8]>(dsm + LS_GS);

    const int dir = blockIdx.y;
    const int u0 = blockIdx.x * 8;
    const int tid = threadIdx.x;
    const int khalf = tid >> 7;          // 0/1: k in [khalf*256, khalf*256+256)
    const int lt = tid & 127;
    const int kbase = khalf * 256;
    const float* W = Whh + (size_t)dir * 2048 * HD;

    // persistent W load (all 256 threads)
    {
        const int lcc = tid & 31;
        const int lgate = lcc >> 3;
        const int lu = u0 + (lcc & 7);
        const int kq8 = tid >> 5;        // 0..7
        for (int kt = 0; kt < HD; kt += 32) {
            float4 v = *reinterpret_cast<const float4*>(
                &W[(size_t)(lgate * HD + lu) * HD + kt + kq8 * 4]);
            Ws[kt + kq8 * 4 + 0][lcc] = v.x; Ws[kt + kq8 * 4 + 1][lcc] = v.y;
            Ws[kt + kq8 * 4 + 2][lcc] = v.z; Ws[kt + kq8 * 4 + 3][lcc] = v.w;
        }
    }

    float cr[4];
    if (khalf == 0) {
#pragma unroll
        for (int i = 0; i < 4; i++) {
            int p = lt + i * 128;
            int b = p >> 3, ul = p & 7;
            size_t idx = (size_t)dir * BB * HD + b * HD + u0 + ul;
            cr[i] = c0[idx];
            hbuf[idx] = h0[idx];
        }
    }
    grid_barrier(128);

    const int b0  = (lt >> 3) * 4;
    const int cg0 = (lt & 7) * 4;
    const int g0  = cg0 >> 3;
    const int ul0 = cg0 & 7;
    const int lb  = lt & 63;
    const int hkq0 = lt >> 6;            // 0/1

    for (int s = 0; s < TT; s++) {
        const int t = dir ? (TT - 1 - s) : s;
        const float* h = hbuf + (size_t)(s & 1) * 2 * BB * HD
                              + (size_t)dir * BB * HD;
        float* ho = hbuf + (size_t)((s + 1) & 1) * 2 * BB * HD
                         + (size_t)dir * BB * HD;

        // preload this khalf's first 16-k chunk
#pragma unroll
        for (int itq = 0; itq < 2; itq++) {
            int kq = hkq0 + itq * 2;
            float4 v = *reinterpret_cast<const float4*>(&h[lb * HD + kbase + kq * 4]);
            Hs[khalf][0][kq * 4 + 0][lb] = v.x; Hs[khalf][0][kq * 4 + 1][lb] = v.y;
            Hs[khalf][0][kq * 4 + 2][lb] = v.z; Hs[khalf][0][kq * 4 + 3][lb] = v.w;
        }
        __syncthreads();

        float acc[4][4];
#pragma unroll
        for (int i = 0; i < 4; i++)
#pragma unroll
            for (int j = 0; j < 4; j++) acc[i][j] = 0.f;

        for (int kt16 = 0; kt16 < 16; kt16++) {
            const int cur = kt16 & 1;
            float4 pv0, pv1;
            const bool pf = (kt16 < 15);
            if (pf) {
                const int kb = kbase + (kt16 + 1) * 16;
                pv0 = *reinterpret_cast<const float4*>(&h[lb * HD + kb + hkq0 * 4]);
                pv1 = *reinterpret_cast<const float4*>(&h[lb * HD + kb + (hkq0 + 2) * 4]);
            }
#pragma unroll
            for (int k = 0; k < 16; k++) {
                float4 hv = *reinterpret_cast<const float4*>(&Hs[khalf][cur][k][b0]);
                float4 wv = *reinterpret_cast<const float4*>(&Ws[kbase + kt16 * 16 + k][cg0]);
                float ar[4] = {hv.x, hv.y, hv.z, hv.w};
                float br[4] = {wv.x, wv.y, wv.z, wv.w};
#pragma unroll
                for (int i = 0; i < 4; i++)
#pragma unroll
                    for (int j = 0; j < 4; j++) acc[i][j] += ar[i] * br[j];
            }
            if (pf) {
                const int nb = cur ^ 1;
                Hs[khalf][nb][hkq0 * 4 + 0][lb] = pv0.x;
                Hs[khalf][nb][hkq0 * 4 + 1][lb] = pv0.y;
                Hs[khalf][nb][hkq0 * 4 + 2][lb] = pv0.z;
                Hs[khalf][nb][hkq0 * 4 + 3][lb] = pv0.w;
                Hs[khalf][nb][(hkq0 + 2) * 4 + 0][lb] = pv1.x;
                Hs[khalf][nb][(hkq0 + 2) * 4 + 1][lb] = pv1.y;
                Hs[khalf][nb][(hkq0 + 2) * 4 + 2][lb] = pv1.z;
                Hs[khalf][nb][(hkq0 + 2) * 4 + 3][lb] = pv1.w;
            }
            __syncthreads();
        }

        // cross-khalf reduction: khalf1 -> red, khalf0 adds
        if (khalf == 1) {
#pragma unroll
            for (int i = 0; i < 4; i++)
#pragma unroll
                for (int j = 0; j < 4; j++)
                    red[i * 4 + j][lt] = acc[i][j];
        }
        __syncthreads();

        if (khalf == 0) {
#pragma unroll
            for (int i = 0; i < 4; i++)
#pragma unroll
                for (int j = 0; j < 4; j++)
                    acc[i][j] += red[i * 4 + j][lt];

            const int row0 = t * BB;
#pragma unroll
            for (int i = 0; i < 4; i++) {
                int b = b0 + i;
                float4 gv = *reinterpret_cast<const float4*>(
                    &G[(size_t)(row0 + b) * NG + dir * 2048 + g0 * HD + u0 + ul0]);
                gs[g0][b][ul0 + 0] = acc[i][0] + gv.x;
                gs[g0][b][ul0 + 1] = acc[i][1] + gv.y;
                gs[g0][b][ul0 + 2] = acc[i][2] + gv.z;
                gs[g0][b][ul0 + 3] = acc[i][3] + gv.w;
            }
        }
        __syncthreads();

        if (khalf == 0) {
#pragma unroll
            for (int i = 0; i < 4; i++) {
                int p = lt + i * 128;
                int b = p >> 3;
                int ul = p & 7;
                int u = u0 + ul;
                float ig = gs[0][b][ul];
                float fg = gs[1][b][ul];
                float gg = gs[2][b][ul];
                float og = gs[3][b][ul];
                float si = 1.f / (1.f + expf(-ig));
                float sf = 1.f / (1.f + expf(-fg));
                float so = 1.f / (1.f + expf(-og));
                float cn = sf * cr[i] + si * tanhf(gg);
                float hn = so * tanhf(cn);
                cr[i] = cn;
                ho[b * HD + u] = hn;
                Hcat[(size_t)t * BB * HH + b * HH + dir * HD + u] = hn;
            }
        }
        grid_barrier(128);
    }
}

// ---------------- final linear ---------------------------------------------------
__global__ void linear_feats(const float* __restrict__ H1,
                             const float* __restrict__ lw,
                             const float* __restrict__ lb,
                             float* __restrict__ feats) {
    int warp = (blockIdx.x * blockDim.x + threadIdx.x) >> 5;
    int lane = threadIdx.x & 31;
    if (warp >= MROWS) return;
    const float* hrow = H1 + (size_t)warp * HH;
    float acc[CC];
#pragma unroll
    for (int c = 0; c < CC; c++) acc[c] = 0.f;
    for (int k = lane; k < HH; k += 32) {
        float hv = hrow[k];
#pragma unroll
        for (int c = 0; c < CC; c++) acc[c] += hv * lw[c * HH + k];
    }
#pragma unroll
    for (int c = 0; c < CC; c++) {
        float v = acc[c];
#pragma unroll
        for (int o = 16; o; o >>= 1) v += __shfl_down_sync(0xffffffffu, v, o);
        if (lane == 0) {
            int t = warp >> 6, b = warp & 63;
            feats[((size_t)b * TT + t) * CC + c] = v + lb[c];
        }
    }
}

// ---------------- Viterbi decode --------------------------------------------------
__global__ void viterbi_kernel(const float* __restrict__ feats,
                               const float* __restrict__ trans,
                               float* __restrict__ out,
                               int write_scores, int write_paths, int path_off) {
    const int b = blockIdx.x;
    const int c = threadIdx.x;
    __shared__ unsigned char bp[TT][CC];

    float tr[CC];
#pragma unroll
    for (int p = 0; p < CC; p++) tr[p] = trans[c * CC + p];

    float fv = (c == START_TAG) ? 0.f : -10000.f;
    const float* f = feats + (size_t)b * TT * CC;

    for (int t = 0; t < TT; t++) {
        float best = -3.4e38f;
        int arg = 0;
#pragma unroll
        for (int p = 0; p < CC; p++) {
            float sc = __shfl_sync(0x0000ffffu, fv, p) + tr[p];
            if (sc > best) { best = sc; arg = p; }
        }
        bp[t][c] = (unsigned char)arg;
        fv = best + f[t * CC + c];
    }

    float term = fv + trans[STOP_TAG * CC + c];
    float bv = term;
    int bi = c;
#pragma unroll
    for (int o = 8; o; o >>= 1) {
        float ov = __shfl_down_sync(0x0000ffffu, bv, o);
        int oi = __shfl_down_sync(0x0000ffffu, bi, o);
        if (ov > bv || (ov == bv && oi < bi)) { bv = ov; bi = oi; }
    }
    bv = __shfl_sync(0x0000ffffu, bv, 0);
    bi = __shfl_sync(0x0000ffffu, bi, 0);

    if (c == 0) {
        if (write_scores) out[b] = bv;
        if (write_paths) {
            int tag = bi;
            for (int t = TT - 1; t >= 0; t--) {
                out[path_off + b * TT + t] = (float)tag;
                tag = bp[t][tag];
            }
        }
    }
}

// ---------------- launch -----------------------------------------------------------
extern "C" void kernel_launch(void* const* d_in, const int* in_sizes, int n_in,
                              void* d_out, int out_size) {
    const int*   sent    = (const int*)  d_in[0];
    const float* emb     = (const float*)d_in[1];
    const float* wih0    = (const float*)d_in[2];
    const float* whh0    = (const float*)d_in[3];
    const float* bih0    = (const float*)d_in[4];
    const float* bhh0    = (const float*)d_in[5];
    const float* wih1    = (const float*)d_in[6];
    const float* whh1    = (const float*)d_in[7];
    const float* bih1    = (const float*)d_in[8];
    const float* bhh1    = (const float*)d_in[9];
    const float* linw    = (const float*)d_in[10];
    const float* linb    = (const float*)d_in[11];
    const float* trans   = (const float*)d_in[12];
    const float* h0      = (const float*)d_in[13];
    const float* c0      = (const float*)d_in[14];

    float *pX0, *pG, *pH0, *pH1, *pfe, *phb;
    __nv_bfloat16 *pAs, *pWs;
    cudaGetSymbolAddress((void**)&pX0, g_X0);
    cudaGetSymbolAddress((void**)&pG,  g_G);
    cudaGetSymbolAddress((void**)&pH0, g_H0);
    cudaGetSymbolAddress((void**)&pH1, g_H1);
    cudaGetSymbolAddress((void**)&pfe, g_feats);
    cudaGetSymbolAddress((void**)&phb, g_hbuf);
    cudaGetSymbolAddress((void**)&pAs, g_As);
    cudaGetSymbolAddress((void**)&pWs, g_Ws);

    cudaFuncSetAttribute(gemm_mma, cudaFuncAttributeMaxDynamicSharedMemorySize,
                         GEMM_SMEM);
    cudaFuncSetAttribute(lstm_layer, cudaFuncAttributeMaxDynamicSharedMemorySize,
                         LSTM_SMEM);

    // 1) embedding gather
    embed_kernel<<<MROWS, 128>>>(sent, emb, pX0);

    // 2) layer-0: split + tensor GEMM (K6 = 3072)
    {
        long long tA = (long long)MROWS * EE;
        long long tW = (long long)NG * EE;
        splitA_kernel<<<(unsigned)((tA + 255) / 256), 256>>>(pX0, pAs, EE, tA);
        splitW_kernel<<<(unsigned)((tW + 255) / 256), 256>>>(wih0, pWs, EE, tW);
        gemm_mma<<<dim3(NG / BN, MROWS / BM), 256, GEMM_SMEM>>>(
            pAs, pWs, bih0, bhh0, pG, 6 * EE);
    }

    // 3) layer-0 recurrence
    lstm_layer<<<dim3(64, 2), 256, LSTM_SMEM>>>(pG, whh0, h0, c0, phb, pH0);

    // 4) layer-1: split + tensor GEMM (K6 = 6144)
    {
        long long tA = (long long)MROWS * HH;
        long long tW = (long long)NG * HH;
        splitA_kernel<<<(unsigned)((tA + 255) / 256), 256>>>(pH0, pAs, HH, tA);
        splitW_kernel<<<(unsigned)((tW + 255) / 256), 256>>>(wih1, pWs, HH, tW);
        gemm_mma<<<dim3(NG / BN, MROWS / BM), 256, GEMM_SMEM>>>(
            pAs, pWs, bih1, bhh1, pG, 6 * HH);
    }

    // 5) layer-1 recurrence
    lstm_layer<<<dim3(64, 2), 256, LSTM_SMEM>>>(pG, whh1,
                                                h0 + 2 * BB * HD, c0 + 2 * BB * HD,
                                                phb, pH1);

    // 6) linear -> feats
    linear_feats<<<(MROWS * 32 + 255) / 256, 256>>>(pH1, linw, linb, pfe);

    // 7) Viterbi decode + output write
    float* out = (float*)d_out;
    int write_scores, write_paths, path_off;
    if (out_size >= BB + BB * TT) { write_scores = 1; write_paths = 1; path_off = BB; }
    else if (out_size == BB * TT) { write_scores = 0; write_paths = 1; path_off = 0; }
    else                          { write_scores = 1; write_paths = 0; path_off = 0; }
    viterbi_kernel<<<BB, CC>>>(pfe, trans, out, write_scores, write_paths, path_off);
}

// round 10
// speedup vs baseline: 1.3273x; 1.1492x over previous
#include <cuda_runtime.h>
#include <cuda_fp16.h>
#include <math.h>
#include <stdint.h>

// Problem dims
#define TT 512
#define BB 64
#define EE 512
#define HD 512
#define HH 1024
#define CC 16
#define START_TAG 14
#define STOP_TAG 15
#define NG 4096          // 2 dirs * 4 gates * HD
#define MROWS (TT*BB)    // 32768

// ---------------- scratch ------------------------------------------------------
__device__ float g_X0[(size_t)MROWS * EE];
__device__ float g_G [(size_t)MROWS * NG];
__device__ float g_H0[(size_t)MROWS * HH];
__device__ float g_H1[(size_t)MROWS * HH];
__device__ __half g_As[(size_t)MROWS * 3 * HH];     // 192 MB (fp16 3-term split)
__device__ __half g_Ws[(size_t)NG * 3 * HH];        //  24 MB
__device__ float g_feats[(size_t)BB * TT * CC];
__device__ float g_hbuf[2 * 2 * BB * HD];

__device__ unsigned int g_bar_count;
__device__ unsigned int g_bar_gen;

__device__ __forceinline__ void grid_barrier(int nblk) {
    __syncthreads();
    if (threadIdx.x == 0) {
        __threadfence();
        unsigned int gen = *(volatile unsigned int*)&g_bar_gen;
        if (atomicAdd(&g_bar_count, 1u) == (unsigned)(nblk - 1)) {
            g_bar_count = 0;
            __threadfence();
            atomicAdd(&g_bar_gen, 1u);
        } else {
            unsigned int cur;
            do {
                asm volatile("ld.acquire.gpu.u32 %0, [%1];"
                             : "=r"(cur) : "l"(&g_bar_gen));
            } while (cur == gen);
        }
    }
    __syncthreads();
}

__device__ __forceinline__ uint32_t smem_u32(const void* p) {
    uint32_t a;
    asm("{ .reg .u64 t; cvta.to.shared.u64 t, %1; cvt.u32.u64 %0, t; }"
        : "=r"(a) : "l"(p));
    return a;
}

// ---------------- embedding gather ---------------------------------------------
__global__ void embed_kernel(const int* __restrict__ sent,
                             const float* __restrict__ emb,
                             float* __restrict__ X0) {
    int m = blockIdx.x;
    int t = m >> 6;
    int b = m & 63;
    int tok = sent[b * TT + t];
    const float4* src = reinterpret_cast<const float4*>(emb + (size_t)tok * EE);
    float4* dst = reinterpret_cast<float4*>(X0 + (size_t)m * EE);
    dst[threadIdx.x] = src[threadIdx.x];
}

// ---------------- fp32 -> 2-term fp16 split, 3 K-concatenated product slots ----
// products: (a0,b0) (a0,b1) (a1,b0); dropped terms ~2^-22 relative.
__global__ void splitA_kernel(const float* __restrict__ X,
                              __half* __restrict__ Y,
                              int K, long long total) {
    long long idx = (long long)blockIdx.x * blockDim.x + threadIdx.x;
    if (idx >= total) return;
    int m = (int)(idx / K);
    int k = (int)(idx % K);
    float a = X[idx];
    __half a0 = __float2half_rn(a);
    float r = a - __half2float(a0);
    __half a1 = __float2half_rn(r);
    __half* base = Y + (size_t)m * 3 * K + k;
    base[0 * K] = a0; base[1 * K] = a0; base[2 * K] = a1;
}
__global__ void splitW_kernel(const float* __restrict__ X,
                              __half* __restrict__ Y,
                              int K, long long total) {
    long long idx = (long long)blockIdx.x * blockDim.x + threadIdx.x;
    if (idx >= total) return;
    int m = (int)(idx / K);
    int k = (int)(idx % K);
    float a = X[idx];
    __half b0 = __float2half_rn(a);
    float r = a - __half2float(b0);
    __half b1 = __float2half_rn(r);
    __half* base = Y + (size_t)m * 3 * K + k;
    base[0 * K] = b0; base[1 * K] = b1; base[2 * K] = b0;
}

// ================= pipelined warp-mma fp16 GEMM (BK=64, BN=256) =================
#define BM 128
#define BN 256
#define BK 64
#define NSTAGE 3
#define PADH 72                               // 64-half row + 8 pad (144B, cf-free)
#define SA_BYTES (BM * PADH * 2)              // 18432
#define SB_BYTES (BN * PADH * 2)              // 36864
#define GEMM_SMEM (NSTAGE * (SA_BYTES + SB_BYTES))   // 165888 -> 1 CTA/SM

__device__ __forceinline__ void ldsm4(uint32_t addr, uint32_t r[4]) {
    asm volatile("ldmatrix.sync.aligned.m8n8.x4.shared.b16 {%0,%1,%2,%3}, [%4];"
                 : "=r"(r[0]), "=r"(r[1]), "=r"(r[2]), "=r"(r[3]) : "r"(addr));
}
__device__ __forceinline__ void mma16816(float c[4], const uint32_t a[4],
                                         const uint32_t b[2]) {
    asm volatile(
        "mma.sync.aligned.m16n8k16.row.col.f32.f16.f16.f32 "
        "{%0,%1,%2,%3}, {%4,%5,%6,%7}, {%8,%9}, {%0,%1,%2,%3};"
        : "+f"(c[0]), "+f"(c[1]), "+f"(c[2]), "+f"(c[3])
        : "r"(a[0]), "r"(a[1]), "r"(a[2]), "r"(a[3]), "r"(b[0]), "r"(b[1]));
}
__device__ __forceinline__ void cp16(uint32_t dst, const void* src) {
    asm volatile("cp.async.cg.shared.global [%0], [%1], 16;" :: "r"(dst), "l"(src));
}
__device__ __forceinline__ void cp_commit() {
    asm volatile("cp.async.commit_group;");
}
template <int N>
__device__ __forceinline__ void cp_wait() {
    asm volatile("cp.async.wait_group %0;" :: "n"(N));
}

__global__ void __launch_bounds__(256, 1)
gemm_mma(const __half* __restrict__ A,
         const __half* __restrict__ W,
         const float* __restrict__ b1,
         const float* __restrict__ b2,
         float* __restrict__ C,
         int K3) {
    extern __shared__ char dsm[];
    const uint32_t sAb = smem_u32(dsm);
    const uint32_t sBb = sAb + NSTAGE * SA_BYTES;

    const int tid = threadIdx.x;
    const int lane = tid & 31;
    const int wid = tid >> 5;
    const int warpm = wid >> 2;     // 0..1 (64 rows)
    const int warpn = wid & 3;      // 0..3 (64 cols)
    const int n0 = blockIdx.x * BN;
    const int m0 = blockIdx.y * BM;

    const int rowoff = ((lane >> 3) & 1) * 8 + (lane & 7);
    const int koffA  = (lane >> 4) * 8;
    const int noff   = ((lane >> 4) << 3) + (lane & 7);
    const int koffB  = ((lane >> 3) & 1) * 8;

    float acc[4][8][4];
#pragma unroll
    for (int i = 0; i < 4; i++)
#pragma unroll
        for (int j = 0; j < 8; j++)
#pragma unroll
            for (int q = 0; q < 4; q++) acc[i][j][q] = 0.f;

    auto issue = [&](int stage, int kt) {
        const int kb = kt * BK;
        const uint32_t sa = sAb + stage * SA_BYTES;
        const uint32_t sb = sBb + stage * SB_BYTES;
#pragma unroll
        for (int q = 0; q < 4; q++) {
            int c = tid + q * 256;
            int r = c >> 3, c8 = c & 7;
            cp16(sa + (uint32_t)(r * PADH + c8 * 8) * 2,
                 A + (size_t)(m0 + r) * K3 + kb + c8 * 8);
        }
#pragma unroll
        for (int q = 0; q < 8; q++) {
            int c = tid + q * 256;
            int r = c >> 3, c8 = c & 7;
            cp16(sb + (uint32_t)(r * PADH + c8 * 8) * 2,
                 W + (size_t)(n0 + r) * K3 + kb + c8 * 8);
        }
    };

    issue(0, 0); cp_commit();
    issue(1, 1); cp_commit();

    const int nkt = K3 / BK;
    int stage = 0;
    for (int kt = 0; kt < nkt; kt++) {
        cp_wait<1>();
        __syncthreads();
        if (kt + 2 < nkt) {
            int ns = stage + 2; if (ns >= NSTAGE) ns -= NSTAGE;
            issue(ns, kt + 2);
        }
        cp_commit();

        const uint32_t sa = sAb + stage * SA_BYTES;
        const uint32_t sb = sBb + stage * SB_BYTES;
#pragma unroll
        for (int ks = 0; ks < 4; ks++) {
            uint32_t af[4][4];
            uint32_t bf[8][2];
#pragma unroll
            for (int mf = 0; mf < 4; mf++) {
                int mrow = warpm * 64 + mf * 16 + rowoff;
                ldsm4(sa + (uint32_t)(mrow * PADH + ks * 16 + koffA) * 2, af[mf]);
            }
#pragma unroll
            for (int p = 0; p < 4; p++) {
                uint32_t rr[4];
                int nrow = warpn * 64 + p * 16 + noff;
                ldsm4(sb + (uint32_t)(nrow * PADH + ks * 16 + koffB) * 2, rr);
                bf[2 * p][0] = rr[0];     bf[2 * p][1] = rr[1];
                bf[2 * p + 1][0] = rr[2]; bf[2 * p + 1][1] = rr[3];
            }
#pragma unroll
            for (int mf = 0; mf < 4; mf++)
#pragma unroll
                for (int nf = 0; nf < 8; nf++)
                    mma16816(acc[mf][nf], af[mf], bf[nf]);
        }
        if (++stage == NSTAGE) stage = 0;
    }

    // epilogue: fp32 + biases
#pragma unroll
    for (int nf = 0; nf < 8; nf++) {
        const int col = n0 + warpn * 64 + nf * 8 + (lane & 3) * 2;
        const float bx = b1[col] + b2[col];
        const float by = b1[col + 1] + b2[col + 1];
#pragma unroll
        for (int mf = 0; mf < 4; mf++) {
            const int row = m0 + warpm * 64 + mf * 16 + (lane >> 2);
            float2 v0 = make_float2(acc[mf][nf][0] + bx, acc[mf][nf][1] + by);
            float2 v1 = make_float2(acc[mf][nf][2] + bx, acc[mf][nf][3] + by);
            *reinterpret_cast<float2*>(C + (size_t)row * NG + col) = v0;
            *reinterpret_cast<float2*>(C + (size_t)(row + 8) * NG + col) = v1;
        }
    }
}

// ---------------- persistent bidirectional LSTM layer (k-split x2) --------------
#define LS_WS  0                              // float Ws[512][32]        = 65536
#define LS_HS  65536                          // float Hs[2][2][16][68]   = 17408
#define LS_RED (65536 + 17408)                // float red[16][128]       = 8192
#define LS_GS  (65536 + 17408 + 8192)         // float gs[4][64][8]       = 8192
#define LSTM_SMEM (LS_GS + 8192)              // 99328

__global__ void __launch_bounds__(256)
lstm_layer(const float* __restrict__ G,
           const float* __restrict__ Whh,
           const float* __restrict__ h0,
           const float* __restrict__ c0,
           float* __restrict__ hbuf,
           float* __restrict__ Hcat) {
    extern __shared__ char dsm[];
    float (*Ws)[32]         = reinterpret_cast<float(*)[32]>(dsm + LS_WS);
    float (*Hs)[2][16][68]  = reinterpret_cast<float(*)[2][16][68]>(dsm + LS_HS);
    float (*red)[128]       = reinterpret_cast<float(*)[128]>(dsm + LS_RED);
    float (*gs)[64][8]      = reinterpret_cast<float(*)[64][8]>(dsm + LS_GS);

    const int dir = blockIdx.y;
    const int u0 = blockIdx.x * 8;
    const int tid = threadIdx.x;
    const int khalf = tid >> 7;
    const int lt = tid & 127;
    const int kbase = khalf * 256;
    const float* W = Whh + (size_t)dir * 2048 * HD;

    {
        const int lcc = tid & 31;
        const int lgate = lcc >> 3;
        const int lu = u0 + (lcc & 7);
        const int kq8 = tid >> 5;
        for (int kt = 0; kt < HD; kt += 32) {
            float4 v = *reinterpret_cast<const float4*>(
                &W[(size_t)(lgate * HD + lu) * HD + kt + kq8 * 4]);
            Ws[kt + kq8 * 4 + 0][lcc] = v.x; Ws[kt + kq8 * 4 + 1][lcc] = v.y;
            Ws[kt + kq8 * 4 + 2][lcc] = v.z; Ws[kt + kq8 * 4 + 3][lcc] = v.w;
        }
    }

    float cr[4];
    if (khalf == 0) {
#pragma unroll
        for (int i = 0; i < 4; i++) {
            int p = lt + i * 128;
            int b = p >> 3, ul = p & 7;
            size_t idx = (size_t)dir * BB * HD + b * HD + u0 + ul;
            cr[i] = c0[idx];
            hbuf[idx] = h0[idx];
        }
    }
    grid_barrier(128);

    const int b0  = (lt >> 3) * 4;
    const int cg0 = (lt & 7) * 4;
    const int g0  = cg0 >> 3;
    const int ul0 = cg0 & 7;
    const int lb  = lt & 63;
    const int hkq0 = lt >> 6;

    for (int s = 0; s < TT; s++) {
        const int t = dir ? (TT - 1 - s) : s;
        const float* h = hbuf + (size_t)(s & 1) * 2 * BB * HD
                              + (size_t)dir * BB * HD;
        float* ho = hbuf + (size_t)((s + 1) & 1) * 2 * BB * HD
                         + (size_t)dir * BB * HD;

#pragma unroll
        for (int itq = 0; itq < 2; itq++) {
            int kq = hkq0 + itq * 2;
            float4 v = *reinterpret_cast<const float4*>(&h[lb * HD + kbase + kq * 4]);
            Hs[khalf][0][kq * 4 + 0][lb] = v.x; Hs[khalf][0][kq * 4 + 1][lb] = v.y;
            Hs[khalf][0][kq * 4 + 2][lb] = v.z; Hs[khalf][0][kq * 4 + 3][lb] = v.w;
        }
        __syncthreads();

        float acc[4][4];
#pragma unroll
        for (int i = 0; i < 4; i++)
#pragma unroll
            for (int j = 0; j < 4; j++) acc[i][j] = 0.f;

        for (int kt16 = 0; kt16 < 16; kt16++) {
            const int cur = kt16 & 1;
            float4 pv0, pv1;
            const bool pf = (kt16 < 15);
            if (pf) {
                const int kb = kbase + (kt16 + 1) * 16;
                pv0 = *reinterpret_cast<const float4*>(&h[lb * HD + kb + hkq0 * 4]);
                pv1 = *reinterpret_cast<const float4*>(&h[lb * HD + kb + (hkq0 + 2) * 4]);
            }
#pragma unroll
            for (int k = 0; k < 16; k++) {
                float4 hv = *reinterpret_cast<const float4*>(&Hs[khalf][cur][k][b0]);
                float4 wv = *reinterpret_cast<const float4*>(&Ws[kbase + kt16 * 16 + k][cg0]);
                float ar[4] = {hv.x, hv.y, hv.z, hv.w};
                float br[4] = {wv.x, wv.y, wv.z, wv.w};
#pragma unroll
                for (int i = 0; i < 4; i++)
#pragma unroll
                    for (int j = 0; j < 4; j++) acc[i][j] += ar[i] * br[j];
            }
            if (pf) {
                const int nb = cur ^ 1;
                Hs[khalf][nb][hkq0 * 4 + 0][lb] = pv0.x;
                Hs[khalf][nb][hkq0 * 4 + 1][lb] = pv0.y;
                Hs[khalf][nb][hkq0 * 4 + 2][lb] = pv0.z;
                Hs[khalf][nb][hkq0 * 4 + 3][lb] = pv0.w;
                Hs[khalf][nb][(hkq0 + 2) * 4 + 0][lb] = pv1.x;
                Hs[khalf][nb][(hkq0 + 2) * 4 + 1][lb] = pv1.y;
                Hs[khalf][nb][(hkq0 + 2) * 4 + 2][lb] = pv1.z;
                Hs[khalf][nb][(hkq0 + 2) * 4 + 3][lb] = pv1.w;
            }
            __syncthreads();
        }

        if (khalf == 1) {
#pragma unroll
            for (int i = 0; i < 4; i++)
#pragma unroll
                for (int j = 0; j < 4; j++)
                    red[i * 4 + j][lt] = acc[i][j];
        }
        __syncthreads();

        if (khalf == 0) {
#pragma unroll
            for (int i = 0; i < 4; i++)
#pragma unroll
                for (int j = 0; j < 4; j++)
                    acc[i][j] += red[i * 4 + j][lt];

            const int row0 = t * BB;
#pragma unroll
            for (int i = 0; i < 4; i++) {
                int b = b0 + i;
                float4 gv = *reinterpret_cast<const float4*>(
                    &G[(size_t)(row0 + b) * NG + dir * 2048 + g0 * HD + u0 + ul0]);
                gs[g0][b][ul0 + 0] = acc[i][0] + gv.x;
                gs[g0][b][ul0 + 1] = acc[i][1] + gv.y;
                gs[g0][b][ul0 + 2] = acc[i][2] + gv.z;
                gs[g0][b][ul0 + 3] = acc[i][3] + gv.w;
            }
        }
        __syncthreads();

        if (khalf == 0) {
#pragma unroll
            for (int i = 0; i < 4; i++) {
                int p = lt + i * 128;
                int b = p >> 3;
                int ul = p & 7;
                int u = u0 + ul;
                float ig = gs[0][b][ul];
                float fg = gs[1][b][ul];
                float gg = gs[2][b][ul];
                float og = gs[3][b][ul];
                float si = 1.f / (1.f + expf(-ig));
                float sf = 1.f / (1.f + expf(-fg));
                float so = 1.f / (1.f + expf(-og));
                float cn = sf * cr[i] + si * tanhf(gg);
                float hn = so * tanhf(cn);
                cr[i] = cn;
                ho[b * HD + u] = hn;
                Hcat[(size_t)t * BB * HH + b * HH + dir * HD + u] = hn;
            }
        }
        grid_barrier(128);
    }
}

// ---------------- final linear ---------------------------------------------------
__global__ void linear_feats(const float* __restrict__ H1,
                             const float* __restrict__ lw,
                             const float* __restrict__ lb,
                             float* __restrict__ feats) {
    int warp = (blockIdx.x * blockDim.x + threadIdx.x) >> 5;
    int lane = threadIdx.x & 31;
    if (warp >= MROWS) return;
    const float* hrow = H1 + (size_t)warp * HH;
    float acc[CC];
#pragma unroll
    for (int c = 0; c < CC; c++) acc[c] = 0.f;
    for (int k = lane; k < HH; k += 32) {
        float hv = hrow[k];
#pragma unroll
        for (int c = 0; c < CC; c++) acc[c] += hv * lw[c * HH + k];
    }
#pragma unroll
    for (int c = 0; c < CC; c++) {
        float v = acc[c];
#pragma unroll
        for (int o = 16; o; o >>= 1) v += __shfl_down_sync(0xffffffffu, v, o);
        if (lane == 0) {
            int t = warp >> 6, b = warp & 63;
            feats[((size_t)b * TT + t) * CC + c] = v + lb[c];
        }
    }
}

// ---------------- Viterbi decode --------------------------------------------------
__global__ void viterbi_kernel(const float* __restrict__ feats,
                               const float* __restrict__ trans,
                               float* __restrict__ out,
                               int write_scores, int write_paths, int path_off) {
    const int b = blockIdx.x;
    const int c = threadIdx.x;
    __shared__ unsigned char bp[TT][CC];

    float tr[CC];
#pragma unroll
    for (int p = 0; p < CC; p++) tr[p] = trans[c * CC + p];

    float fv = (c == START_TAG) ? 0.f : -10000.f;
    const float* f = feats + (size_t)b * TT * CC;

    for (int t = 0; t < TT; t++) {
        float best = -3.4e38f;
        int arg = 0;
#pragma unroll
        for (int p = 0; p < CC; p++) {
            float sc = __shfl_sync(0x0000ffffu, fv, p) + tr[p];
            if (sc > best) { best = sc; arg = p; }
        }
        bp[t][c] = (unsigned char)arg;
        fv = best + f[t * CC + c];
    }

    float term = fv + trans[STOP_TAG * CC + c];
    float bv = term;
    int bi = c;
#pragma unroll
    for (int o = 8; o; o >>= 1) {
        float ov = __shfl_down_sync(0x0000ffffu, bv, o);
        int oi = __shfl_down_sync(0x0000ffffu, bi, o);
        if (ov > bv || (ov == bv && oi < bi)) { bv = ov; bi = oi; }
    }
    bv = __shfl_sync(0x0000ffffu, bv, 0);
    bi = __shfl_sync(0x0000ffffu, bi, 0);

    if (c == 0) {
        if (write_scores) out[b] = bv;
        if (write_paths) {
            int tag = bi;
            for (int t = TT - 1; t >= 0; t--) {
                out[path_off + b * TT + t] = (float)tag;
                tag = bp[t][tag];
            }
        }
    }
}

// ---------------- launch -----------------------------------------------------------
extern "C" void kernel_launch(void* const* d_in, const int* in_sizes, int n_in,
                              void* d_out, int out_size) {
    const int*   sent    = (const int*)  d_in[0];
    const float* emb     = (const float*)d_in[1];
    const float* wih0    = (const float*)d_in[2];
    const float* whh0    = (const float*)d_in[3];
    const float* bih0    = (const float*)d_in[4];
    const float* bhh0    = (const float*)d_in[5];
    const float* wih1    = (const float*)d_in[6];
    const float* whh1    = (const float*)d_in[7];
    const float* bih1    = (const float*)d_in[8];
    const float* bhh1    = (const float*)d_in[9];
    const float* linw    = (const float*)d_in[10];
    const float* linb    = (const float*)d_in[11];
    const float* trans   = (const float*)d_in[12];
    const float* h0      = (const float*)d_in[13];
    const float* c0      = (const float*)d_in[14];

    float *pX0, *pG, *pH0, *pH1, *pfe, *phb;
    __half *pAs, *pWs;
    cudaGetSymbolAddress((void**)&pX0, g_X0);
    cudaGetSymbolAddress((void**)&pG,  g_G);
    cudaGetSymbolAddress((void**)&pH0, g_H0);
    cudaGetSymbolAddress((void**)&pH1, g_H1);
    cudaGetSymbolAddress((void**)&pfe, g_feats);
    cudaGetSymbolAddress((void**)&phb, g_hbuf);
    cudaGetSymbolAddress((void**)&pAs, g_As);
    cudaGetSymbolAddress((void**)&pWs, g_Ws);

    cudaFuncSetAttribute(gemm_mma, cudaFuncAttributeMaxDynamicSharedMemorySize,
                         GEMM_SMEM);
    cudaFuncSetAttribute(lstm_layer, cudaFuncAttributeMaxDynamicSharedMemorySize,
                         LSTM_SMEM);

    // 1) embedding gather
    embed_kernel<<<MROWS, 128>>>(sent, emb, pX0);

    // 2) layer-0: split + tensor GEMM (K3 = 1536)
    {
        long long tA = (long long)MROWS * EE;
        long long tW = (long long)NG * EE;
        splitA_kernel<<<(unsigned)((tA + 255) / 256), 256>>>(pX0, pAs, EE, tA);
        splitW_kernel<<<(unsigned)((tW + 255) / 256), 256>>>(wih0, pWs, EE, tW);
        gemm_mma<<<dim3(NG / BN, MROWS / BM), 256, GEMM_SMEM>>>(
            pAs, pWs, bih0, bhh0, pG, 3 * EE);
    }

    // 3) layer-0 recurrence
    lstm_layer<<<dim3(64, 2), 256, LSTM_SMEM>>>(pG, whh0, h0, c0, phb, pH0);

    // 4) layer-1: split + tensor GEMM (K3 = 3072)
    {
        long long tA = (long long)MROWS * HH;
        long long tW = (long long)NG * HH;
        splitA_kernel<<<(unsigned)((tA + 255) / 256), 256>>>(pH0, pAs, HH, tA);
        splitW_kernel<<<(unsigned)((tW + 255) / 256), 256>>>(wih1, pWs, HH, tW);
        gemm_mma<<<dim3(NG / BN, MROWS / BM), 256, GEMM_SMEM>>>(
            pAs, pWs, bih1, bhh1, pG, 3 * HH);
    }

    // 5) layer-1 recurrence
    lstm_layer<<<dim3(64, 2), 256, LSTM_SMEM>>>(pG, whh1,
                                                h0 + 2 * BB * HD, c0 + 2 * BB * HD,
                                                phb, pH1);

    // 6) linear -> feats
    linear_feats<<<(MROWS * 32 + 255) / 256, 256>>>(pH1, linw, linb, pfe);

    // 7) Viterbi decode + output write
    float* out = (float*)d_out;
    int write_scores, write_paths, path_off;
    if (out_size >= BB + BB * TT) { write_scores = 1; write_paths = 1; path_off = BB; }
    else if (out_size == BB * TT) { write_scores = 0; write_paths = 1; path_off = 0; }
    else                          { write_scores = 1; write_paths = 0; path_off = 0; }
    viterbi_kernel<<<BB, CC>>>(pfe, trans, out, write_scores, write_paths, path_off);
}

// round 12
// speedup vs baseline: 2.0510x; 1.5453x over previous
#include <cuda_runtime.h>
#include <cuda_fp16.h>
#include <math.h>
#include <stdint.h>

// Problem dims
#define TT 512
#define BB 64
#define EE 512
#define HD 512
#define HH 1024
#define CC 16
#define START_TAG 14
#define STOP_TAG 15
#define NG 4096          // 2 dirs * 4 gates * HD
#define MROWS (TT*BB)    // 32768

// ---------------- scratch ------------------------------------------------------
__device__ float g_X0[(size_t)MROWS * EE];
__device__ float g_G [(size_t)MROWS * NG];
__device__ float g_H0[(size_t)MROWS * HH];
__device__ float g_H1[(size_t)MROWS * HH];
__device__ __half g_As[(size_t)MROWS * 3 * HH];          // fp16 3-slot split A
__device__ __half g_Ws[(size_t)NG * 3 * HH];             // fp16 3-slot split W_ih
__device__ __half g_Whsp[2][(size_t)2 * 2048 * 1536];    // per-layer split+reordered Whh
__device__ __half g_hsplit[2][2][64 * 1536];             // [parity][dir][b][k3]
__device__ float g_feats[(size_t)BB * TT * CC];

__device__ unsigned int g_dbar_count[2];
__device__ unsigned int g_dbar_gen[2];

__device__ __forceinline__ void grid_barrier_dir(int dir, int nblk) {
    __syncthreads();
    if (threadIdx.x == 0) {
        __threadfence();
        unsigned int gen = *(volatile unsigned int*)&g_dbar_gen[dir];
        if (atomicAdd(&g_dbar_count[dir], 1u) == (unsigned)(nblk - 1)) {
            g_dbar_count[dir] = 0;
            __threadfence();
            atomicAdd(&g_dbar_gen[dir], 1u);
        } else {
            unsigned int cur;
            do {
                asm volatile("ld.acquire.gpu.u32 %0, [%1];"
                             : "=r"(cur) : "l"(&g_dbar_gen[dir]));
            } while (cur == gen);
        }
    }
    __syncthreads();
}

__device__ __forceinline__ uint32_t smem_u32(const void* p) {
    uint32_t a;
    asm("{ .reg .u64 t; cvta.to.shared.u64 t, %1; cvt.u32.u64 %0, t; }"
        : "=r"(a) : "l"(p));
    return a;
}

// ---------------- embedding gather ---------------------------------------------
__global__ void embed_kernel(const int* __restrict__ sent,
                             const float* __restrict__ emb,
                             float* __restrict__ X0) {
    int m = blockIdx.x;
    int t = m >> 6;
    int b = m & 63;
    int tok = sent[b * TT + t];
    const float4* src = reinterpret_cast<const float4*>(emb + (size_t)tok * EE);
    float4* dst = reinterpret_cast<float4*>(X0 + (size_t)m * EE);
    dst[threadIdx.x] = src[threadIdx.x];
}

// ---------------- fp32 -> 2-term fp16 split, 3 product slots --------------------
__global__ void splitA_kernel(const float* __restrict__ X,
                              __half* __restrict__ Y,
                              int K, long long total) {
    long long idx = (long long)blockIdx.x * blockDim.x + threadIdx.x;
    if (idx >= total) return;
    int m = (int)(idx / K);
    int k = (int)(idx % K);
    float a = X[idx];
    __half a0 = __float2half_rn(a);
    float r = a - __half2float(a0);
    __half a1 = __float2half_rn(r);
    __half* base = Y + (size_t)m * 3 * K + k;
    base[0 * K] = a0; base[1 * K] = a0; base[2 * K] = a1;
}
__global__ void splitW_kernel(const float* __restrict__ X,
                              __half* __restrict__ Y,
                              int K, long long total) {
    long long idx = (long long)blockIdx.x * blockDim.x + threadIdx.x;
    if (idx >= total) return;
    int m = (int)(idx / K);
    int k = (int)(idx % K);
    float a = X[idx];
    __half b0 = __float2half_rn(a);
    float r = a - __half2float(b0);
    __half b1 = __float2half_rn(r);
    __half* base = Y + (size_t)m * 3 * K + k;
    base[0 * K] = b0; base[1 * K] = b1; base[2 * K] = b0;
}

// ---------------- Whh -> split fp16 with gate-major row reorder -----------------
__global__ void splitWhh_kernel(const float* __restrict__ W,
                                __half* __restrict__ Y) {
    long long idx = (long long)blockIdx.x * blockDim.x + threadIdx.x;
    if (idx >= (long long)2 * 2048 * 512) return;
    int k = (int)(idx & 511);
    int row = (int)((idx >> 9) & 2047);
    int dir = (int)(idx >> 20);
    float a = W[idx];
    __half w0 = __float2half_rn(a);
    float r = a - __half2float(w0);
    __half w1 = __float2half_rn(r);
    int g = row >> 9;
    int u = row & 511;
    int rnew = (u >> 3) * 32 + g * 8 + (u & 7);
    __half* base = Y + ((size_t)dir * 2048 + rnew) * 1536 + k;
    base[0] = w0; base[512] = w1; base[1024] = w0;
}

// ---------------- mma / cp.async helpers ----------------------------------------
__device__ __forceinline__ void ldsm4(uint32_t addr, uint32_t r[4]) {
    asm volatile("ldmatrix.sync.aligned.m8n8.x4.shared.b16 {%0,%1,%2,%3}, [%4];"
                 : "=r"(r[0]), "=r"(r[1]), "=r"(r[2]), "=r"(r[3]) : "r"(addr));
}
__device__ __forceinline__ void ldsm2(uint32_t addr, uint32_t r[2]) {
    asm volatile("ldmatrix.sync.aligned.m8n8.x2.shared.b16 {%0,%1}, [%2];"
                 : "=r"(r[0]), "=r"(r[1]) : "r"(addr));
}
__device__ __forceinline__ void mma16816(float c[4], const uint32_t a[4],
                                         const uint32_t b[2]) {
    asm volatile(
        "mma.sync.aligned.m16n8k16.row.col.f32.f16.f16.f32 "
        "{%0,%1,%2,%3}, {%4,%5,%6,%7}, {%8,%9}, {%0,%1,%2,%3};"
        : "+f"(c[0]), "+f"(c[1]), "+f"(c[2]), "+f"(c[3])
        : "r"(a[0]), "r"(a[1]), "r"(a[2]), "r"(a[3]), "r"(b[0]), "r"(b[1]));
}
__device__ __forceinline__ void cp16(uint32_t dst, const void* src) {
    asm volatile("cp.async.cg.shared.global [%0], [%1], 16;" :: "r"(dst), "l"(src));
}
__device__ __forceinline__ void cp_commit() {
    asm volatile("cp.async.commit_group;");
}
template <int N>
__device__ __forceinline__ void cp_wait() {
    asm volatile("cp.async.wait_group %0;" :: "n"(N));
}

// ================= pipelined warp-mma fp16 GEMM (BK=64, BN=256) =================
#define BM 128
#define BN 256
#define BK 64
#define NSTAGE 3
#define PADH 72
#define SA_BYTES (BM * PADH * 2)
#define SB_BYTES (BN * PADH * 2)
#define GEMM_SMEM (NSTAGE * (SA_BYTES + SB_BYTES))

__global__ void __launch_bounds__(256, 1)
gemm_mma(const __half* __restrict__ A,
         const __half* __restrict__ W,
         const float* __restrict__ b1,
         const float* __restrict__ b2,
         float* __restrict__ C,
         int K3) {
    extern __shared__ char dsm[];
    const uint32_t sAb = smem_u32(dsm);
    const uint32_t sBb = sAb + NSTAGE * SA_BYTES;

    const int tid = threadIdx.x;
    const int lane = tid & 31;
    const int wid = tid >> 5;
    const int warpm = wid >> 2;
    const int warpn = wid & 3;
    const int n0 = blockIdx.x * BN;
    const int m0 = blockIdx.y * BM;

    const int rowoff = ((lane >> 3) & 1) * 8 + (lane & 7);
    const int koffA  = (lane >> 4) * 8;
    const int noff   = ((lane >> 4) << 3) + (lane & 7);
    const int koffB  = ((lane >> 3) & 1) * 8;

    float acc[4][8][4];
#pragma unroll
    for (int i = 0; i < 4; i++)
#pragma unroll
        for (int j = 0; j < 8; j++)
#pragma unroll
            for (int q = 0; q < 4; q++) acc[i][j][q] = 0.f;

    auto issue = [&](int stage, int kt) {
        const int kb = kt * BK;
        const uint32_t sa = sAb + stage * SA_BYTES;
        const uint32_t sb = sBb + stage * SB_BYTES;
#pragma unroll
        for (int q = 0; q < 4; q++) {
            int c = tid + q * 256;
            int r = c >> 3, c8 = c & 7;
            cp16(sa + (uint32_t)(r * PADH + c8 * 8) * 2,
                 A + (size_t)(m0 + r) * K3 + kb + c8 * 8);
        }
#pragma unroll
        for (int q = 0; q < 8; q++) {
            int c = tid + q * 256;
            int r = c >> 3, c8 = c & 7;
            cp16(sb + (uint32_t)(r * PADH + c8 * 8) * 2,
                 W + (size_t)(n0 + r) * K3 + kb + c8 * 8);
        }
    };

    issue(0, 0); cp_commit();
    issue(1, 1); cp_commit();

    const int nkt = K3 / BK;
    int stage = 0;
    for (int kt = 0; kt < nkt; kt++) {
        cp_wait<1>();
        __syncthreads();
        if (kt + 2 < nkt) {
            int ns = stage + 2; if (ns >= NSTAGE) ns -= NSTAGE;
            issue(ns, kt + 2);
        }
        cp_commit();

        const uint32_t sa = sAb + stage * SA_BYTES;
        const uint32_t sb = sBb + stage * SB_BYTES;
#pragma unroll
        for (int ks = 0; ks < 4; ks++) {
            uint32_t af[4][4];
            uint32_t bf[8][2];
#pragma unroll
            for (int mf = 0; mf < 4; mf++) {
                int mrow = warpm * 64 + mf * 16 + rowoff;
                ldsm4(sa + (uint32_t)(mrow * PADH + ks * 16 + koffA) * 2, af[mf]);
            }
#pragma unroll
            for (int p = 0; p < 4; p++) {
                uint32_t rr[4];
                int nrow = warpn * 64 + p * 16 + noff;
                ldsm4(sb + (uint32_t)(nrow * PADH + ks * 16 + koffB) * 2, rr);
                bf[2 * p][0] = rr[0];     bf[2 * p][1] = rr[1];
                bf[2 * p + 1][0] = rr[2]; bf[2 * p + 1][1] = rr[3];
            }
#pragma unroll
            for (int mf = 0; mf < 4; mf++)
#pragma unroll
                for (int nf = 0; nf < 8; nf++)
                    mma16816(acc[mf][nf], af[mf], bf[nf]);
        }
        if (++stage == NSTAGE) stage = 0;
    }

#pragma unroll
    for (int nf = 0; nf < 8; nf++) {
        const int col = n0 + warpn * 64 + nf * 8 + (lane & 3) * 2;
        const float bx = b1[col] + b2[col];
        const float by = b1[col + 1] + b2[col + 1];
#pragma unroll
        for (int mf = 0; mf < 4; mf++) {
            const int row = m0 + warpm * 64 + mf * 16 + (lane >> 2);
            float2 v0 = make_float2(acc[mf][nf][0] + bx, acc[mf][nf][1] + by);
            float2 v1 = make_float2(acc[mf][nf][2] + bx, acc[mf][nf][3] + by);
            *reinterpret_cast<float2*>(C + (size_t)row * NG + col) = v0;
            *reinterpret_cast<float2*>(C + (size_t)(row + 8) * NG + col) = v1;
        }
    }
}

// ================= tensor-core persistent LSTM layer ============================
// grid (64, 2): x = unit block (8 units, 32 reordered gate-cols), y = dir.
// 512 threads = 16 warps: warpm = wid>>2 in 0..3 (16 M-rows each, one m16n8
// fragment), warpn = wid&3 == gate. FIX vs R11: warpm range now matches 16 warps.
#define LKC 256                              // k-chunk (halves)
#define LNC 6                                // 1536 / 256 chunks
#define LAPAD 264                            // A chunk row stride (halves)
#define LWPAD 1544                           // W row stride (halves)
#define LW_OFF 0                             // W: 32*1544*2      = 98816
#define LA_OFF 98816                         // A: 3*64*264*2     = 101376
#define LG_OFF (98816 + 101376)              // gs: 4*64*8*4      = 8192
#define LSTM_SMEM (LG_OFF + 8192)            // 208384

__global__ void __launch_bounds__(512, 1)
lstm_layer(const float* __restrict__ G,
           const __half* __restrict__ Wsp,   // [2][2048][1536] reordered split
           const float* __restrict__ h0,
           const float* __restrict__ c0,
           __half* __restrict__ hsplit,      // [2][2][64*1536]
           float* __restrict__ Hcat) {
    extern __shared__ char dsm[];
    const uint32_t sW = smem_u32(dsm) + LW_OFF;
    const uint32_t sA = smem_u32(dsm) + LA_OFF;
    float (*gs)[64][8] = reinterpret_cast<float(*)[64][8]>(dsm + LG_OFF);

    const int dir = blockIdx.y;
    const int nb = blockIdx.x;           // 0..63
    const int u0 = nb * 8;
    const int tid = threadIdx.x;
    const int lane = tid & 31;
    const int wid = tid >> 5;            // 0..15
    const int warpm = wid >> 2;          // 0..3  (16 rows each)
    const int warpn = wid & 3;           // 0..3 == gate

    // ---- load W slice (32 rows x 1536) into persistent smem ----
    {
        const __half* wsrc = Wsp + ((size_t)dir * 2048 + nb * 32) * 1536;
        for (int q = 0; q < 12; q++) {
            int id = tid + q * 512;
            int r = id / 192, c8 = id % 192;
            uint4 v = *reinterpret_cast<const uint4*>(wsrc + (size_t)r * 1536 + c8 * 8);
            *reinterpret_cast<uint4*>(dsm + LW_OFF + (r * LWPAD + c8 * 8) * 2) = v;
        }
    }

    // ---- init: c->reg, split h0 into hsplit parity 0 ----
    const int cb = tid >> 3;             // batch 0..63
    const int cj = tid & 7;              // unit j
    float cr = c0[(size_t)dir * BB * HD + cb * HD + u0 + cj];
    {
        float hv = h0[(size_t)dir * BB * HD + cb * HD + u0 + cj];
        __half v0 = __float2half_rn(hv);
        __half v1 = __float2half_rn(hv - __half2float(v0));
        __half* hp = hsplit + ((size_t)0 * 2 + dir) * 64 * 1536 + cb * 1536;
        hp[u0 + cj] = v0;
        hp[512 + u0 + cj] = v0;
        hp[1024 + u0 + cj] = v1;
    }
    grid_barrier_dir(dir, 64);

    const int rowoff = ((lane >> 3) & 1) * 8 + (lane & 7);
    const int koffA  = (lane >> 4) * 8;
    const int brow   = warpn * 8 + (lane & 7);
    const int koffB  = ((lane >> 3) & 1) * 8;

    for (int s = 0; s < TT; s++) {
        const int t = dir ? (TT - 1 - s) : s;
        const __half* hin = hsplit + ((size_t)(s & 1) * 2 + dir) * 64 * 1536;
        __half* hout = hsplit + ((size_t)((s + 1) & 1) * 2 + dir) * 64 * 1536;

        auto issueA = [&](int stg, int kc) {
#pragma unroll
            for (int q = 0; q < 4; q++) {
                int id = tid + q * 512;
                int r = id >> 5, c8 = id & 31;
                cp16(sA + stg * (64 * LAPAD * 2) + (uint32_t)(r * LAPAD + c8 * 8) * 2,
                     hin + (size_t)r * 1536 + kc * LKC + c8 * 8);
            }
        };

        issueA(0, 0); cp_commit();
        issueA(1, 1); cp_commit();

        float acc[4];
#pragma unroll
        for (int q = 0; q < 4; q++) acc[q] = 0.f;

        int stage = 0;
        for (int kc = 0; kc < LNC; kc++) {
            cp_wait<1>();
            __syncthreads();
            if (kc + 2 < LNC) {
                int ns = stage + 2; if (ns >= 3) ns -= 3;
                issueA(ns, kc + 2);
            }
            cp_commit();

            const uint32_t sa = sA + stage * (64 * LAPAD * 2);
#pragma unroll
            for (int ks = 0; ks < LKC / 16; ks++) {
                uint32_t bfr[2];
                ldsm2(sW + (uint32_t)(brow * LWPAD + kc * LKC + ks * 16 + koffB) * 2, bfr);
                uint32_t af[4];
                int mrow = warpm * 16 + rowoff;       // <= 63
                ldsm4(sa + (uint32_t)(mrow * LAPAD + ks * 16 + koffA) * 2, af);
                mma16816(acc, af, bfr);
            }
            if (++stage == 3) stage = 0;
        }

        // add G and stage gates in smem (warpn == gate)
        {
            const int j0 = (lane & 3) * 2;
            const size_t gcol = (size_t)dir * 2048 + warpn * 512 + u0 + j0;
            int m1 = warpm * 16 + (lane >> 2);        // <= 55
            int m2 = m1 + 8;                          // <= 63
            float2 g1 = *reinterpret_cast<const float2*>(
                &G[(size_t)(t * BB + m1) * NG + gcol]);
            float2 g2 = *reinterpret_cast<const float2*>(
                &G[(size_t)(t * BB + m2) * NG + gcol]);
            gs[warpn][m1][j0]     = acc[0] + g1.x;
            gs[warpn][m1][j0 + 1] = acc[1] + g1.y;
            gs[warpn][m2][j0]     = acc[2] + g2.x;
            gs[warpn][m2][j0 + 1] = acc[3] + g2.y;
        }
        __syncthreads();

        // cell update: thread -> (batch cb, unit cj)
        {
            float ig = gs[0][cb][cj];
            float fg = gs[1][cb][cj];
            float gg = gs[2][cb][cj];
            float og = gs[3][cb][cj];
            float si = 1.f / (1.f + expf(-ig));
            float sf = 1.f / (1.f + expf(-fg));
            float so = 1.f / (1.f + expf(-og));
            float cn = sf * cr + si * tanhf(gg);
            float hn = so * tanhf(cn);
            cr = cn;
            Hcat[(size_t)t * BB * HH + cb * HH + dir * HD + u0 + cj] = hn;
            __half v0 = __float2half_rn(hn);
            __half v1 = __float2half_rn(hn - __half2float(v0));
            __half* hp = hout + (size_t)cb * 1536;
            hp[u0 + cj] = v0;
            hp[512 + u0 + cj] = v0;
            hp[1024 + u0 + cj] = v1;
        }
        grid_barrier_dir(dir, 64);
    }
}

// ---------------- final linear ---------------------------------------------------
__global__ void linear_feats(const float* __restrict__ H1,
                             const float* __restrict__ lw,
                             const float* __restrict__ lb,
                             float* __restrict__ feats) {
    int warp = (blockIdx.x * blockDim.x + threadIdx.x) >> 5;
    int lane = threadIdx.x & 31;
    if (warp >= MROWS) return;
    const float* hrow = H1 + (size_t)warp * HH;
    float acc[CC];
#pragma unroll
    for (int c = 0; c < CC; c++) acc[c] = 0.f;
    for (int k = lane; k < HH; k += 32) {
        float hv = hrow[k];
#pragma unroll
        for (int c = 0; c < CC; c++) acc[c] += hv * lw[c * HH + k];
    }
#pragma unroll
    for (int c = 0; c < CC; c++) {
        float v = acc[c];
#pragma unroll
        for (int o = 16; o; o >>= 1) v += __shfl_down_sync(0xffffffffu, v, o);
        if (lane == 0) {
            int t = warp >> 6, b = warp & 63;
            feats[((size_t)b * TT + t) * CC + c] = v + lb[c];
        }
    }
}

// ---------------- Viterbi decode --------------------------------------------------
__global__ void viterbi_kernel(const float* __restrict__ feats,
                               const float* __restrict__ trans,
                               float* __restrict__ out,
                               int write_scores, int write_paths, int path_off) {
    const int b = blockIdx.x;
    const int c = threadIdx.x;
    __shared__ unsigned char bp[TT][CC];

    float tr[CC];
#pragma unroll
    for (int p = 0; p < CC; p++) tr[p] = trans[c * CC + p];

    float fv = (c == START_TAG) ? 0.f : -10000.f;
    const float* f = feats + (size_t)b * TT * CC;

    for (int t = 0; t < TT; t++) {
        float best = -3.4e38f;
        int arg = 0;
#pragma unroll
        for (int p = 0; p < CC; p++) {
            float sc = __shfl_sync(0x0000ffffu, fv, p) + tr[p];
            if (sc > best) { best = sc; arg = p; }
        }
        bp[t][c] = (unsigned char)arg;
        fv = best + f[t * CC + c];
    }

    float term = fv + trans[STOP_TAG * CC + c];
    float bv = term;
    int bi = c;
#pragma unroll
    for (int o = 8; o; o >>= 1) {
        float ov = __shfl_down_sync(0x0000ffffu, bv, o);
        int oi = __shfl_down_sync(0x0000ffffu, bi, o);
        if (ov > bv || (ov == bv && oi < bi)) { bv = ov; bi = oi; }
    }
    bv = __shfl_sync(0x0000ffffu, bv, 0);
    bi = __shfl_sync(0x0000ffffu, bi, 0);

    if (c == 0) {
        if (write_scores) out[b] = bv;
        if (write_paths) {
            int tag = bi;
            for (int t = TT - 1; t >= 0; t--) {
                out[path_off + b * TT + t] = (float)tag;
                tag = bp[t][tag];
            }
        }
    }
}

// ---------------- launch -----------------------------------------------------------
extern "C" void kernel_launch(void* const* d_in, const int* in_sizes, int n_in,
                              void* d_out, int out_size) {
    const int*   sent    = (const int*)  d_in[0];
    const float* emb     = (const float*)d_in[1];
    const float* wih0    = (const float*)d_in[2];
    const float* whh0    = (const float*)d_in[3];
    const float* bih0    = (const float*)d_in[4];
    const float* bhh0    = (const float*)d_in[5];
    const float* wih1    = (const float*)d_in[6];
    const float* whh1    = (const float*)d_in[7];
    const float* bih1    = (const float*)d_in[8];
    const float* bhh1    = (const float*)d_in[9];
    const float* linw    = (const float*)d_in[10];
    const float* linb    = (const float*)d_in[11];
    const float* trans   = (const float*)d_in[12];
    const float* h0      = (const float*)d_in[13];
    const float* c0      = (const float*)d_in[14];

    float *pX0, *pG, *pH0, *pH1, *pfe;
    __half *pAs, *pWs, *pWh0, *pWh1, *phs;
    cudaGetSymbolAddress((void**)&pX0, g_X0);
    cudaGetSymbolAddress((void**)&pG,  g_G);
    cudaGetSymbolAddress((void**)&pH0, g_H0);
    cudaGetSymbolAddress((void**)&pH1, g_H1);
    cudaGetSymbolAddress((void**)&pfe, g_feats);
    cudaGetSymbolAddress((void**)&pAs, g_As);
    cudaGetSymbolAddress((void**)&pWs, g_Ws);
    cudaGetSymbolAddress((void**)&pWh0, g_Whsp);
    pWh1 = pWh0 + (size_t)2 * 2048 * 1536;
    cudaGetSymbolAddress((void**)&phs, g_hsplit);

    cudaFuncSetAttribute(gemm_mma, cudaFuncAttributeMaxDynamicSharedMemorySize,
                         GEMM_SMEM);
    cudaFuncSetAttribute(lstm_layer, cudaFuncAttributeMaxDynamicSharedMemorySize,
                         LSTM_SMEM);

    // 1) embedding gather + recurrent-weight splits
    embed_kernel<<<MROWS, 128>>>(sent, emb, pX0);
    {
        long long tWh = (long long)2 * 2048 * 512;
        splitWhh_kernel<<<(unsigned)((tWh + 255) / 256), 256>>>(whh0, pWh0);
        splitWhh_kernel<<<(unsigned)((tWh + 255) / 256), 256>>>(whh1, pWh1);
    }

    // 2) layer-0: split + tensor GEMM (K3 = 1536)
    {
        long long tA = (long long)MROWS * EE;
        long long tW = (long long)NG * EE;
        splitA_kernel<<<(unsigned)((tA + 255) / 256), 256>>>(pX0, pAs, EE, tA);
        splitW_kernel<<<(unsigned)((tW + 255) / 256), 256>>>(wih0, pWs, EE, tW);
        gemm_mma<<<dim3(NG / BN, MROWS / BM), 256, GEMM_SMEM>>>(
            pAs, pWs, bih0, bhh0, pG, 3 * EE);
    }

    // 3) layer-0 recurrence (tensor cores)
    lstm_layer<<<dim3(64, 2), 512, LSTM_SMEM>>>(pG, pWh0, h0, c0, phs, pH0);

    // 4) layer-1: split + tensor GEMM (K3 = 3072)
    {
        long long tA = (long long)MROWS * HH;
        long long tW = (long long)NG * HH;
        splitA_kernel<<<(unsigned)((tA + 255) / 256), 256>>>(pH0, pAs, HH, tA);
        splitW_kernel<<<(unsigned)((tW + 255) / 256), 256>>>(wih1, pWs, HH, tW);
        gemm_mma<<<dim3(NG / BN, MROWS / BM), 256, GEMM_SMEM>>>(
            pAs, pWs, bih1, bhh1, pG, 3 * HH);
    }

    // 5) layer-1 recurrence
    lstm_layer<<<dim3(64, 2), 512, LSTM_SMEM>>>(pG, pWh1,
                                                h0 + 2 * BB * HD, c0 + 2 * BB * HD,
                                                phs, pH1);

    // 6) linear -> feats
    linear_feats<<<(MROWS * 32 + 255) / 256, 256>>>(pH1, linw, linb, pfe);

    // 7) Viterbi decode + output write
    float* out = (float*)d_out;
    int write_scores, write_paths, path_off;
    if (out_size >= BB + BB * TT) { write_scores = 1; write_paths = 1; path_off = BB; }
    else if (out_size == BB * TT) { write_scores = 0; write_paths = 1; path_off = 0; }
    else                          { write_scores = 1; write_paths = 0; path_off = 0; }
    viterbi_kernel<<<BB, CC>>>(pfe, trans, out, write_scores, write_paths, path_off);
}